// round 4
// baseline (speedup 1.0000x reference)
#include <cuda_runtime.h>
#include <cstdint>

// ---------------- problem constants ----------------
// B=64 N=16 C=16 T=256 DH=128 DT=8 DP=128 TOUT=32 P=4 DIN=136
#define NB   64
#define NN   16
#define NC   16
#define NT   256
#define NDH  128
#define NDT  8
#define NDP  128
#define NTOUT 32
#define NDIN 136

// ---------------- scratch (static device arrays; no allocation) ----------------
__device__ float g_Hc [64u*16u*256u*136u];   // [bm*T+t][136]  142MB
__device__ float g_P  [64u*16u*256u*256u];   // [row][0:128]=Hc*Wn^T, [128:256]=Hc*Wself^T
__device__ float g_Z  [64u*16u*256u*128u];   // [row][128]
__device__ float g_K  [1024u*128u*256u];     // [m][d][t]  (transposed for decoder)
__device__ float g_V  [1024u*256u*128u];     // [m][t][d]
__device__ float g_WhhT [16*128*384];        // [n][k][g]
__device__ float g_Wcat [256*136];           // rows 0..127 = Wn (spectral-normed), 128..255 = W_self
__device__ float g_Wkv  [256*128];           // rows 0..127 = Wk, 128..255 = Wv
__device__ float g_cWihT[144*384];           // [k][g]
__device__ float g_cWhhT[128*384];           // [k][g]
__device__ float g_Aph  [4*16*16];           // per-phase graph
__device__ float g_utab [256*8];             // tanh(t*tW+tb)
__device__ float g_h   [1024*128];
__device__ float g_y   [1024*16];
__device__ float g_ymix[1024*16];
__device__ float g_ctx [1024*128];
__device__ float g_scale[1];

__device__ __forceinline__ float sigm(float x){ return 1.0f/(1.0f+expf(-x)); }

// ---------------- K0: spectral norm, phase graphs, u table, weight packs ----------------
__global__ void __launch_bounds__(256) k0_prep(
    const float* __restrict__ Wneigh, const float* __restrict__ Wself,
    const float* __restrict__ Wk, const float* __restrict__ Wv,
    const float* __restrict__ S, const float* __restrict__ G,
    const float* __restrict__ tW, const float* __restrict__ tb,
    const float* __restrict__ ltau)
{
    __shared__ float u[128], v[136], red[256], sig;
    int tid = threadIdx.x;
    if (tid < 128) u[tid] = 1.0f / sqrtf(128.0f);
    __syncthreads();
    for (int it = 0; it < 15; it++) {
        float vv = 0.f;
        if (tid < 136) { float s = 0.f; for (int i = 0; i < 128; i++) s += Wneigh[i*136+tid]*u[i]; vv = s; }
        red[tid] = (tid < 136) ? vv*vv : 0.f; __syncthreads();
        for (int o = 128; o > 0; o >>= 1) { if (tid < o) red[tid] += red[tid+o]; __syncthreads(); }
        float nv = sqrtf(red[0]); __syncthreads();
        if (tid < 136) v[tid] = vv / nv;
        __syncthreads();
        float uu = 0.f;
        if (tid < 128) { float s = 0.f; for (int j = 0; j < 136; j++) s += Wneigh[tid*136+j]*v[j]; uu = s; }
        red[tid] = (tid < 128) ? uu*uu : 0.f; __syncthreads();
        for (int o = 128; o > 0; o >>= 1) { if (tid < o) red[tid] += red[tid+o]; __syncthreads(); }
        float nu = sqrtf(red[0]); __syncthreads();
        if (tid < 128) u[tid] = uu / nu;
        __syncthreads();
    }
    {
        float p = 0.f;
        if (tid < 128) { float s = 0.f; for (int j = 0; j < 136; j++) s += Wneigh[tid*136+j]*v[j]; p = u[tid]*s; }
        red[tid] = p; __syncthreads();
        for (int o = 128; o > 0; o >>= 1) { if (tid < o) red[tid] += red[tid+o]; __syncthreads(); }
        if (tid == 0) sig = red[0];
        __syncthreads();
    }
    float inv = 1.0f / sig;
    for (int i = tid; i < 128*136; i += 256) { g_Wcat[i] = Wneigh[i]*inv; g_Wcat[17408+i] = Wself[i]; }
    for (int i = tid; i < 128*128; i += 256) { g_Wkv[i] = Wk[i]; g_Wkv[16384+i] = Wv[i]; }
    for (int i = tid; i < 256*8;   i += 256) { int t = i >> 3, j = i & 7;
        g_utab[i] = tanhf(((float)t * (1.0f/255.0f)) * tW[j] + tb[j]); }
    if (tid == 0) g_scale[0] = expf(ltau[0]);
    if (tid < 4) {
        int p = tid; float gg[16]; float gs = 0.f;
        for (int i = 0; i < 16; i++) { float x = G[p*16+i]; float sp = log1pf(expf(x)) + 1e-6f; gg[i] = sp; gs += sp; }
        float gn = 16.0f / fmaxf(gs, 1e-6f);
        for (int i = 0; i < 16; i++) {
            float den = 0.f;
            for (int j = 0; j < 16; j++) { float sv = (i==j) ? 0.f : S[p*256+i*16+j]; den += fabsf(sv); }
            den = fmaxf(den, 1e-6f);
            float gi = gg[i]*gn;
            for (int j = 0; j < 16; j++) { float sv = (i==j) ? 0.f : S[p*256+i*16+j];
                g_Aph[p*256+i*16+j] = sv/den*gi; }
        }
    }
}

// ---------------- weight transposes ----------------
__global__ void k_trans(const float* __restrict__ Whh,
                        const float* __restrict__ cWih, const float* __restrict__ cWhh)
{
    int i = blockIdx.x*256 + threadIdx.x;
    const int T1 = 16*384*128, T2 = 384*144, T3 = 384*128;
    if (i < T1) {
        int n = i / 49152, r = i % 49152, gg = r / 128, k = r % 128;
        g_WhhT[n*49152 + k*384 + gg] = Whh[i];
    } else if (i < T1 + T2) {
        int j = i - T1; int gg = j / 144, k = j % 144;
        g_cWihT[k*384 + gg] = cWih[j];
    } else if (i < T1 + T2 + T3) {
        int j = i - T1 - T2; int gg = j / 128, k = j % 128;
        g_cWhhT[k*384 + gg] = cWhh[j];
    }
}

// ---------------- K2: GRU scan over T with fused Gx compute + LN, writes Hc ----------------
// dynamic smem layout (floats):
//   h_s   [0,1024)      sA [1024,2048)  sB [2048,3072)  sXn [3072,4096)  sHn [4096,5120)
//   Wih_s [5120,11264)  (16c x 384g)
//   Xs    [11264,19456) ([c][tc][b] : c*512 + tc*8 + b, tc in 64-chunk)
//   lg [19456,19584) lb [19584,19712) red1 [19712,19744) red2 [19744,19776)
#define K2_SMEM_FLOATS 19776
__global__ void __launch_bounds__(384) k2_gru(const float* __restrict__ X,
                                              const float* __restrict__ Wih,
                                              const float* __restrict__ bih,
                                              const float* __restrict__ bhh,
                                              const float* __restrict__ lng,
                                              const float* __restrict__ lnb)
{
    extern __shared__ float sm[];
    float* h_s   = sm;
    float* sA    = sm + 1024;
    float* sB    = sm + 2048;
    float* sXn   = sm + 3072;
    float* sHn   = sm + 4096;
    float* Wih_s = sm + 5120;
    float* Xs    = sm + 11264;
    float* lg    = sm + 19456;
    float* lb    = sm + 19584;
    float* red1  = sm + 19712;
    float* red2  = sm + 19744;

    int g = threadIdx.x;
    int n = blockIdx.x >> 3, bg = blockIdx.x & 7;
    if (g < 128) { lg[g] = lng[g]; lb[g] = lnb[g]; }
    for (int i = g; i < 1024; i += 384) h_s[i] = 0.f;
    // Wih_s[c][g2] = Wih[n][g2][c]
    for (int i = g; i < 6144; i += 384) { int g2 = i >> 4, c = i & 15;
        Wih_s[c*384 + g2] = Wih[n*6144 + i]; }
    float bhh_g = bhh[n*384 + g];
    float bih_g = bih[n*384 + g];
    const float* wp = g_WhhT + n*49152 + g;
    __syncthreads();

    for (int t = 0; t < 256; t++) {
        int tc = t & 63;
        if (tc == 0) {
            __syncthreads();
            // load X chunk: Xs[c*512 + tcc*8 + b] = X[((bg*8+b)*16+n)*4096 + c*256 + t + tcc]
            for (int i = g; i < 8192; i += 384) {
                int b = i >> 10, r = i & 1023, c = r >> 6, tcc = r & 63;
                Xs[c*512 + tcc*8 + b] = X[(size_t)((bg*8 + b)*16 + n)*4096 + c*256 + t + tcc];
            }
            __syncthreads();
        }
        float acc[8], gx[8];
        #pragma unroll
        for (int b = 0; b < 8; b++) { acc[b] = 0.f; gx[b] = bih_g; }
        // Gx on the fly: 16 c-iterations
        #pragma unroll
        for (int c = 0; c < 16; c++) {
            float w = Wih_s[c*384 + g];
            float4 xA = *(const float4*)(Xs + c*512 + tc*8);
            float4 xB = *(const float4*)(Xs + c*512 + tc*8 + 4);
            gx[0] = fmaf(w, xA.x, gx[0]); gx[1] = fmaf(w, xA.y, gx[1]);
            gx[2] = fmaf(w, xA.z, gx[2]); gx[3] = fmaf(w, xA.w, gx[3]);
            gx[4] = fmaf(w, xB.x, gx[4]); gx[5] = fmaf(w, xB.y, gx[5]);
            gx[6] = fmaf(w, xB.z, gx[6]); gx[7] = fmaf(w, xB.w, gx[7]);
        }
        // Whh @ h
        #pragma unroll 4
        for (int k = 0; k < 128; k++) {
            float w = wp[(size_t)k*384];
            float4 hA = *(const float4*)(h_s + k*8);
            float4 hB = *(const float4*)(h_s + k*8 + 4);
            acc[0] = fmaf(w, hA.x, acc[0]); acc[1] = fmaf(w, hA.y, acc[1]);
            acc[2] = fmaf(w, hA.z, acc[2]); acc[3] = fmaf(w, hA.w, acc[3]);
            acc[4] = fmaf(w, hB.x, acc[4]); acc[5] = fmaf(w, hB.y, acc[5]);
            acc[6] = fmaf(w, hB.z, acc[6]); acc[7] = fmaf(w, hB.w, acc[7]);
        }
        if (g < 128) {
            #pragma unroll
            for (int b = 0; b < 8; b++) sA[g*8 + b] = gx[b] + acc[b] + bhh_g;
        } else if (g < 256) {
            #pragma unroll
            for (int b = 0; b < 8; b++) sB[(g-128)*8 + b] = gx[b] + acc[b] + bhh_g;
        } else {
            #pragma unroll
            for (int b = 0; b < 8; b++) { sXn[(g-256)*8 + b] = gx[b]; sHn[(g-256)*8 + b] = acc[b] + bhh_g; }
        }
        __syncthreads();
        float hnew[8];
        if (g < 128) {
            float s1[8], s2[8];
            #pragma unroll
            for (int b = 0; b < 8; b++) {
                float r  = sigm(sA[g*8 + b]);
                float z  = sigm(sB[g*8 + b]);
                float nn = tanhf(sXn[g*8 + b] + r*sHn[g*8 + b]);
                float hv = (1.f - z)*nn + z*h_s[g*8 + b];
                hnew[b] = hv; h_s[g*8 + b] = hv;
                s1[b] = hv; s2[b] = hv*hv;
            }
            #pragma unroll
            for (int off = 16; off > 0; off >>= 1) {
                #pragma unroll
                for (int b = 0; b < 8; b++) {
                    s1[b] += __shfl_down_sync(0xffffffffu, s1[b], off);
                    s2[b] += __shfl_down_sync(0xffffffffu, s2[b], off);
                }
            }
            if ((g & 31) == 0) { int w = g >> 5;
                #pragma unroll
                for (int b = 0; b < 8; b++) { red1[w*8 + b] = s1[b]; red2[w*8 + b] = s2[b]; }
            }
        }
        __syncthreads();
        if (g < 128) {
            #pragma unroll
            for (int b = 0; b < 8; b++) {
                float mean = (red1[b] + red1[8+b] + red1[16+b] + red1[24+b]) * 0.0078125f;
                float msq  = (red2[b] + red2[8+b] + red2[16+b] + red2[24+b]) * 0.0078125f;
                float var  = msq - mean*mean;
                float rstd = rsqrtf(var + 1e-5f);
                int bm = (bg*8 + b)*16 + n;
                g_Hc[((size_t)bm*256 + t)*136 + g] = (hnew[b] - mean)*rstd*lg[g] + lb[g];
            }
        } else if (g < 136) {
            float uv = g_utab[t*8 + (g - 128)];
            #pragma unroll
            for (int b = 0; b < 8; b++) {
                int bm = (bg*8 + b)*16 + n;
                g_Hc[((size_t)bm*256 + t)*136 + g] = uv;
            }
        }
        __syncthreads();
    }
}

// ---------------- K3: P = Hc @ Wcat^T   (262144 x 136) @ (136 x 256) ----------------
__global__ void __launch_bounds__(256) k3_gemm_hc()
{
    const int KD = 136;
    __shared__ float As[1024], Bs[1024];
    int tid = threadIdx.x;
    size_t row0 = (size_t)blockIdx.x*128; int col0 = blockIdx.y*128;
    int lr = tid >> 1, lq = (tid & 1)*4;
    const float* Ag = g_Hc + (row0 + lr)*KD + lq;
    const float* Bg = g_Wcat + (size_t)(col0 + lr)*KD + lq;
    float acc[8][8];
    #pragma unroll
    for (int i = 0; i < 8; i++) {
        #pragma unroll
        for (int j = 0; j < 8; j++) acc[i][j] = 0.f;
    }
    int tr = tid >> 4, tc = tid & 15;
    for (int k0 = 0; k0 < KD; k0 += 8) {
        float4 a4 = *(const float4*)(Ag + k0);
        float4 b4 = *(const float4*)(Bg + k0);
        As[(lq+0)*128 + lr] = a4.x; As[(lq+1)*128 + lr] = a4.y;
        As[(lq+2)*128 + lr] = a4.z; As[(lq+3)*128 + lr] = a4.w;
        Bs[(lq+0)*128 + lr] = b4.x; Bs[(lq+1)*128 + lr] = b4.y;
        Bs[(lq+2)*128 + lr] = b4.z; Bs[(lq+3)*128 + lr] = b4.w;
        __syncthreads();
        #pragma unroll
        for (int kk = 0; kk < 8; kk++) {
            float af[8], bf[8];
            *(float4*)(af)   = *(const float4*)(As + kk*128 + tr*8);
            *(float4*)(af+4) = *(const float4*)(As + kk*128 + tr*8 + 4);
            *(float4*)(bf)   = *(const float4*)(Bs + kk*128 + tc*8);
            *(float4*)(bf+4) = *(const float4*)(Bs + kk*128 + tc*8 + 4);
            #pragma unroll
            for (int i = 0; i < 8; i++)
                #pragma unroll
                for (int j = 0; j < 8; j++) acc[i][j] = fmaf(af[i], bf[j], acc[i][j]);
        }
        __syncthreads();
    }
    #pragma unroll
    for (int i = 0; i < 8; i++) {
        size_t row = row0 + tr*8 + i;
        float* cp = g_P + row*256 + col0 + tc*8;
        *(float4*)cp     = make_float4(acc[i][0], acc[i][1], acc[i][2], acc[i][3]);
        *(float4*)(cp+4) = make_float4(acc[i][4], acc[i][5], acc[i][6], acc[i][7]);
    }
}

// ---------------- K4: graph mix + self + leaky -> Z ----------------
__global__ void __launch_bounds__(256) k4_mix(const int* __restrict__ phases)
{
    __shared__ float Am[256], sP[2048];
    int tid = threadIdx.x; int b = blockIdx.y; int t0 = blockIdx.x*8;
    Am[tid] = g_Aph[phases[b]*256 + tid];
    for (int tc = 0; tc < 8; tc++) {
        int t = t0 + tc;
        __syncthreads();
        for (int idx = tid; idx < 2048; idx += 256) { int j = idx >> 7, d = idx & 127;
            sP[idx] = g_P[((size_t)(b*16 + j)*256 + t)*256 + d]; }
        __syncthreads();
        for (int idx = tid; idx < 2048; idx += 256) {
            int i = idx >> 7, d = idx & 127;
            size_t row = (size_t)(b*16 + i)*256 + t;
            float accv = g_P[row*256 + 128 + d];
            #pragma unroll
            for (int j = 0; j < 16; j++) accv = fmaf(Am[i*16 + j], sP[j*128 + d], accv);
            g_Z[row*128 + d] = (accv >= 0.f) ? accv : 0.1f*accv;
        }
    }
}

// ---------------- K5: K|V = Z @ Wkv^T ; K stored [m][d][t], V stored [m][t][d] ----------------
__global__ void __launch_bounds__(256) k5_gemm_kv()
{
    const int KD = 128;
    __shared__ float As[1024], Bs[1024];
    int tid = threadIdx.x;
    size_t row0 = (size_t)blockIdx.x*128; int col0 = blockIdx.y*128;
    int lr = tid >> 1, lq = (tid & 1)*4;
    const float* Ag = g_Z + (row0 + lr)*KD + lq;
    const float* Bg = g_Wkv + (size_t)(col0 + lr)*KD + lq;
    float acc[8][8];
    #pragma unroll
    for (int i = 0; i < 8; i++) {
        #pragma unroll
        for (int j = 0; j < 8; j++) acc[i][j] = 0.f;
    }
    int tr = tid >> 4, tc = tid & 15;
    for (int k0 = 0; k0 < KD; k0 += 8) {
        float4 a4 = *(const float4*)(Ag + k0);
        float4 b4 = *(const float4*)(Bg + k0);
        As[(lq+0)*128 + lr] = a4.x; As[(lq+1)*128 + lr] = a4.y;
        As[(lq+2)*128 + lr] = a4.z; As[(lq+3)*128 + lr] = a4.w;
        Bs[(lq+0)*128 + lr] = b4.x; Bs[(lq+1)*128 + lr] = b4.y;
        Bs[(lq+2)*128 + lr] = b4.z; Bs[(lq+3)*128 + lr] = b4.w;
        __syncthreads();
        #pragma unroll
        for (int kk = 0; kk < 8; kk++) {
            float af[8], bf[8];
            *(float4*)(af)   = *(const float4*)(As + kk*128 + tr*8);
            *(float4*)(af+4) = *(const float4*)(As + kk*128 + tr*8 + 4);
            *(float4*)(bf)   = *(const float4*)(Bs + kk*128 + tc*8);
            *(float4*)(bf+4) = *(const float4*)(Bs + kk*128 + tc*8 + 4);
            #pragma unroll
            for (int i = 0; i < 8; i++)
                #pragma unroll
                for (int j = 0; j < 8; j++) acc[i][j] = fmaf(af[i], bf[j], acc[i][j]);
        }
        __syncthreads();
    }
    #pragma unroll
    for (int i = 0; i < 8; i++) {
        int row = (int)row0 + tr*8 + i;
        int m = row >> 8, t = row & 255;
        if (col0 == 0) { // K half: transpose store [m][d][t]
            #pragma unroll
            for (int j = 0; j < 8; j++)
                g_K[(size_t)m*32768 + (size_t)(tc*8 + j)*256 + t] = acc[i][j];
        } else {         // V half: [m][t][d]
            float* vp = g_V + (size_t)row*128 + tc*8;
            *(float4*)vp     = make_float4(acc[i][0], acc[i][1], acc[i][2], acc[i][3]);
            *(float4*)(vp+4) = make_float4(acc[i][4], acc[i][5], acc[i][6], acc[i][7]);
        }
    }
}

// ---------------- K6: decode init ----------------
__global__ void k6_init()
{
    int i = blockIdx.x*256 + threadIdx.x;
    if (i < 1024*128) { int m = i >> 7, d = i & 127;
        g_h[i] = g_Z[((size_t)m*256 + 255)*128 + d]; }
    if (i < 1024*16) g_y[i] = 0.f;
}

// ---------------- D1: y-mix + attention -> ctx ----------------
__global__ void __launch_bounds__(256) d1_attn(const int* __restrict__ phases)
{
    __shared__ float ys[256], h_s[128], sc[256], red[256], cp[256], arow[16];
    int tid = threadIdx.x; int m = blockIdx.x; int b = m >> 4, n = m & 15;
    ys[tid] = g_y[b*256 + tid];
    if (tid < 16) arow[tid] = g_Aph[phases[b]*256 + n*16 + tid];
    if (tid < 128) h_s[tid] = g_h[m*128 + tid];
    __syncthreads();
    if (tid < 16) {
        float a = 0.f;
        #pragma unroll
        for (int j = 0; j < 16; j++) a = fmaf(arow[j], ys[j*16 + tid], a);
        g_ymix[m*16 + tid] = ys[n*16 + tid] + 0.3f*a;
    }
    float scale = g_scale[0];
    const float* kp = g_K + (size_t)m*32768 + tid;
    float s = 0.f;
    #pragma unroll 8
    for (int d = 0; d < 128; d++) s = fmaf(kp[(size_t)d*256], h_s[d], s);
    s *= scale;
    red[tid] = s; __syncthreads();
    for (int o = 128; o > 0; o >>= 1) { if (tid < o) red[tid] = fmaxf(red[tid], red[tid+o]); __syncthreads(); }
    float mx = red[0]; __syncthreads();
    float e = expf(s - mx);
    red[tid] = e; __syncthreads();
    for (int o = 128; o > 0; o >>= 1) { if (tid < o) red[tid] += red[tid+o]; __syncthreads(); }
    float inv = 1.0f / red[0];
    sc[tid] = e * inv; __syncthreads();
    int d = tid & 127, half = tid >> 7;
    const float* vp = g_V + ((size_t)m*256 + half*128)*128 + d;
    float accv = 0.f;
    #pragma unroll 8
    for (int tt = 0; tt < 128; tt++) accv = fmaf(sc[half*128 + tt], vp[(size_t)tt*128], accv);
    cp[tid] = accv; __syncthreads();
    if (tid < 128) g_ctx[m*128 + tid] = cp[tid] + cp[tid + 128];
}

// ---------------- D2: GRU cell + readout + output write ----------------
__global__ void __launch_bounds__(384) d2_cell(const float* __restrict__ X,
                                               const float* __restrict__ cbih,
                                               const float* __restrict__ cbhh,
                                               const float* __restrict__ readW,
                                               const float* __restrict__ readb,
                                               float* __restrict__ out, int step)
{
    __shared__ float inp[144], h_s[128], sA[128], sB[128], sXn[128], sHn[128], hn_s[128];
    int g = threadIdx.x; int m = blockIdx.x;
    if (g < 128) { h_s[g] = g_h[m*128 + g]; inp[g] = g_ctx[m*128 + g]; }
    else if (g < 144) inp[g] = g_ymix[m*16 + (g - 128)];
    __syncthreads();
    float gx = cbih[g], gh = cbhh[g];
    const float* wi = g_cWihT + g;
    #pragma unroll 8
    for (int k = 0; k < 144; k++) gx = fmaf(wi[(size_t)k*384], inp[k], gx);
    const float* wh = g_cWhhT + g;
    #pragma unroll 8
    for (int k = 0; k < 128; k++) gh = fmaf(wh[(size_t)k*384], h_s[k], gh);
    if (g < 128) sA[g] = gx + gh;
    else if (g < 256) sB[g - 128] = gx + gh;
    else { sXn[g - 256] = gx; sHn[g - 256] = gh; }
    __syncthreads();
    if (g < 128) {
        float r  = sigm(sA[g]);
        float z  = sigm(sB[g]);
        float nn = tanhf(sXn[g] + r*sHn[g]);
        float hv = (1.f - z)*nn + z*h_s[g];
        g_h[m*128 + g] = hv; hn_s[g] = hv;
    }
    __syncthreads();
    if (g < 128) {
        int c = g >> 3, r8 = g & 7;
        const float* rw = readW + c*128 + r8*16;
        const float* hp = hn_s + r8*16;
        float a = 0.f;
        #pragma unroll
        for (int i = 0; i < 16; i++) a = fmaf(rw[i], hp[i], a);
        a += __shfl_down_sync(0xffffffffu, a, 4, 8);
        a += __shfl_down_sync(0xffffffffu, a, 2, 8);
        a += __shfl_down_sync(0xffffffffu, a, 1, 8);
        if (r8 == 0) {
            float yt = a + readb[c] + inp[128 + c];
            g_y[m*16 + c] = yt;
            float vv = X[(size_t)(m*16 + c)*256 + 255] + yt;
            out[(m*16 + c)*32 + step] = vv;
            if (step == 0) out[524288 + m*16 + c] = vv;
        }
    }
}

// ---------------- host launch ----------------
extern "C" void kernel_launch(void* const* d_in, const int* in_sizes, int n_in,
                              void* d_out, int out_size)
{
    const float* X      = (const float*)d_in[0];
    const int*   phases = (const int*)  d_in[1];
    const float* gWih   = (const float*)d_in[2];
    const float* gWhh   = (const float*)d_in[3];
    const float* gbih   = (const float*)d_in[4];
    const float* gbhh   = (const float*)d_in[5];
    const float* lng    = (const float*)d_in[6];
    const float* lnb    = (const float*)d_in[7];
    const float* tW     = (const float*)d_in[8];
    const float* tb     = (const float*)d_in[9];
    const float* S      = (const float*)d_in[10];
    const float* G      = (const float*)d_in[11];
    const float* Wself  = (const float*)d_in[12];
    const float* Wneigh = (const float*)d_in[13];
    const float* cWih   = (const float*)d_in[14];
    const float* cWhh   = (const float*)d_in[15];
    const float* cbih   = (const float*)d_in[16];
    const float* cbhh   = (const float*)d_in[17];
    const float* readW  = (const float*)d_in[18];
    const float* readb  = (const float*)d_in[19];
    const float* Wk     = (const float*)d_in[20];
    const float* Wv     = (const float*)d_in[21];
    const float* ltau   = (const float*)d_in[22];
    float* out = (float*)d_out;

    const int k2_smem = K2_SMEM_FLOATS * (int)sizeof(float);
    cudaFuncSetAttribute(k2_gru, cudaFuncAttributeMaxDynamicSharedMemorySize, k2_smem);

    k0_prep<<<1, 256>>>(Wneigh, Wself, Wk, Wv, S, G, tW, tb, ltau);
    {
        int total = 16*384*128 + 384*144 + 384*128;
        k_trans<<<(total + 255)/256, 256>>>(gWhh, cWih, cWhh);
    }
    k2_gru<<<128, 384, k2_smem>>>(X, gWih, gbih, gbhh, lng, lnb);
    k3_gemm_hc<<<dim3(2048, 2), 256>>>();
    k4_mix<<<dim3(32, 64), 256>>>(phases);
    k5_gemm_kv<<<dim3(2048, 2), 256>>>();
    k6_init<<<512, 256>>>();
    for (int s = 0; s < 32; s++) {
        d1_attn<<<1024, 256>>>(phases);
        d2_cell<<<1024, 384>>>(X, cbih, cbhh, readW, readb, out, s);
    }
    (void)in_sizes; (void)n_in; (void)out_size;
}

// round 7
// speedup vs baseline: 1.0073x; 1.0073x over previous
#include <cuda_runtime.h>
#include <cuda_fp16.h>
#include <cstdint>

// ---------------- problem constants ----------------
// B=64 N=16 C=16 T=256 DH=128 DT=8 DP=128 TOUT=32 P=4 DIN=136

// ---------------- scratch (static device arrays; no allocation) ----------------
__device__ float g_Hc [64u*16u*256u*136u];   // [bm*T+t][136]  142MB
__device__ float g_P  [64u*16u*256u*256u];   // [row][0:128]=Hc*Wn^T, [128:256]=Hc*Wself^T
__device__ float g_Z  [64u*16u*256u*128u];   // [row][128]
__device__ __half g_K [1024u*128u*256u];     // [m][d][t]  fp16 (transposed for decoder)
__device__ __half g_V [1024u*256u*128u];     // [m][t][d]  fp16
__device__ float g_WhhT [16*128*384];        // [n][k][g]
__device__ float g_Wcat [256*136];           // rows 0..127 = Wn (spectral-normed), 128..255 = W_self
__device__ float g_Wkv  [256*128];           // rows 0..127 = Wk, 128..255 = Wv
__device__ float g_cWihT[144*384];           // [k][g]
__device__ float g_cWhhT[128*384];           // [k][g]
__device__ float g_Aph  [4*16*16];           // per-phase graph
__device__ float g_utab [256*8];             // tanh(t*tW+tb)
__device__ float g_h   [1024*128];
__device__ float g_yA  [1024*16];            // ping-pong y state (fixes cross-block race)
__device__ float g_yB  [1024*16];
__device__ float g_scale[1];

__device__ __forceinline__ float sigm(float x){ return 1.0f/(1.0f+expf(-x)); }

// ---------------- K0: spectral norm, phase graphs, u table, weight packs ----------------
__global__ void __launch_bounds__(256) k0_prep(
    const float* __restrict__ Wneigh, const float* __restrict__ Wself,
    const float* __restrict__ Wk, const float* __restrict__ Wv,
    const float* __restrict__ S, const float* __restrict__ G,
    const float* __restrict__ tW, const float* __restrict__ tb,
    const float* __restrict__ ltau)
{
    __shared__ float u[128], v[136], red[256], sig;
    int tid = threadIdx.x;
    if (tid < 128) u[tid] = 1.0f / sqrtf(128.0f);
    __syncthreads();
    for (int it = 0; it < 15; it++) {
        float vv = 0.f;
        if (tid < 136) { float s = 0.f; for (int i = 0; i < 128; i++) s += Wneigh[i*136+tid]*u[i]; vv = s; }
        red[tid] = (tid < 136) ? vv*vv : 0.f; __syncthreads();
        for (int o = 128; o > 0; o >>= 1) { if (tid < o) red[tid] += red[tid+o]; __syncthreads(); }
        float nv = sqrtf(red[0]); __syncthreads();
        if (tid < 136) v[tid] = vv / nv;
        __syncthreads();
        float uu = 0.f;
        if (tid < 128) { float s = 0.f; for (int j = 0; j < 136; j++) s += Wneigh[tid*136+j]*v[j]; uu = s; }
        red[tid] = (tid < 128) ? uu*uu : 0.f; __syncthreads();
        for (int o = 128; o > 0; o >>= 1) { if (tid < o) red[tid] += red[tid+o]; __syncthreads(); }
        float nu = sqrtf(red[0]); __syncthreads();
        if (tid < 128) u[tid] = uu / nu;
        __syncthreads();
    }
    {
        float p = 0.f;
        if (tid < 128) { float s = 0.f; for (int j = 0; j < 136; j++) s += Wneigh[tid*136+j]*v[j]; p = u[tid]*s; }
        red[tid] = p; __syncthreads();
        for (int o = 128; o > 0; o >>= 1) { if (tid < o) red[tid] += red[tid+o]; __syncthreads(); }
        if (tid == 0) sig = red[0];
        __syncthreads();
    }
    float inv = 1.0f / sig;
    for (int i = tid; i < 128*136; i += 256) { g_Wcat[i] = Wneigh[i]*inv; g_Wcat[17408+i] = Wself[i]; }
    for (int i = tid; i < 128*128; i += 256) { g_Wkv[i] = Wk[i]; g_Wkv[16384+i] = Wv[i]; }
    for (int i = tid; i < 256*8;   i += 256) { int t = i >> 3, j = i & 7;
        g_utab[i] = tanhf(((float)t * (1.0f/255.0f)) * tW[j] + tb[j]); }
    if (tid == 0) g_scale[0] = expf(ltau[0]);
    if (tid < 4) {
        int p = tid; float gg[16]; float gs = 0.f;
        for (int i = 0; i < 16; i++) { float x = G[p*16+i]; float sp = log1pf(expf(x)) + 1e-6f; gg[i] = sp; gs += sp; }
        float gn = 16.0f / fmaxf(gs, 1e-6f);
        for (int i = 0; i < 16; i++) {
            float den = 0.f;
            for (int j = 0; j < 16; j++) { float sv = (i==j) ? 0.f : S[p*256+i*16+j]; den += fabsf(sv); }
            den = fmaxf(den, 1e-6f);
            float gi = gg[i]*gn;
            for (int j = 0; j < 16; j++) { float sv = (i==j) ? 0.f : S[p*256+i*16+j];
                g_Aph[p*256+i*16+j] = sv/den*gi; }
        }
    }
}

// ---------------- weight transposes ----------------
__global__ void k_trans(const float* __restrict__ Whh,
                        const float* __restrict__ cWih, const float* __restrict__ cWhh)
{
    int i = blockIdx.x*256 + threadIdx.x;
    const int T1 = 16*384*128, T2 = 384*144, T3 = 384*128;
    if (i < T1) {
        int n = i / 49152, r = i % 49152, gg = r / 128, k = r % 128;
        g_WhhT[n*49152 + k*384 + gg] = Whh[i];
    } else if (i < T1 + T2) {
        int j = i - T1; int gg = j / 144, k = j % 144;
        g_cWihT[k*384 + gg] = cWih[j];
    } else if (i < T1 + T2 + T3) {
        int j = i - T1 - T2; int gg = j / 128, k = j % 128;
        g_cWhhT[k*384 + gg] = cWhh[j];
    }
}

// ---------------- K2: GRU scan over T with fused Gx compute + LN, writes Hc ----------------
#define K2_SMEM_FLOATS 19776
__global__ void __launch_bounds__(384) k2_gru(const float* __restrict__ X,
                                              const float* __restrict__ Wih,
                                              const float* __restrict__ bih,
                                              const float* __restrict__ bhh,
                                              const float* __restrict__ lng,
                                              const float* __restrict__ lnb)
{
    extern __shared__ float sm[];
    float* h_s   = sm;
    float* sA    = sm + 1024;
    float* sB    = sm + 2048;
    float* sXn   = sm + 3072;
    float* sHn   = sm + 4096;
    float* Wih_s = sm + 5120;
    float* Xs    = sm + 11264;
    float* lg    = sm + 19456;
    float* lb    = sm + 19584;
    float* red1  = sm + 19712;
    float* red2  = sm + 19744;

    int g = threadIdx.x;
    int n = blockIdx.x >> 3, bg = blockIdx.x & 7;
    if (g < 128) { lg[g] = lng[g]; lb[g] = lnb[g]; }
    for (int i = g; i < 1024; i += 384) h_s[i] = 0.f;
    for (int i = g; i < 6144; i += 384) { int g2 = i >> 4, c = i & 15;
        Wih_s[c*384 + g2] = Wih[n*6144 + i]; }
    float bhh_g = bhh[n*384 + g];
    float bih_g = bih[n*384 + g];
    const float* wp = g_WhhT + n*49152 + g;
    __syncthreads();

    for (int t = 0; t < 256; t++) {
        int tc = t & 63;
        if (tc == 0) {
            __syncthreads();
            for (int i = g; i < 8192; i += 384) {
                int b = i >> 10, r = i & 1023, c = r >> 6, tcc = r & 63;
                Xs[c*512 + tcc*8 + b] = X[(size_t)((bg*8 + b)*16 + n)*4096 + c*256 + t + tcc];
            }
            __syncthreads();
        }
        float acc[8], gx[8];
        #pragma unroll
        for (int b = 0; b < 8; b++) { acc[b] = 0.f; gx[b] = bih_g; }
        #pragma unroll
        for (int c = 0; c < 16; c++) {
            float w = Wih_s[c*384 + g];
            float4 xA = *(const float4*)(Xs + c*512 + tc*8);
            float4 xB = *(const float4*)(Xs + c*512 + tc*8 + 4);
            gx[0] = fmaf(w, xA.x, gx[0]); gx[1] = fmaf(w, xA.y, gx[1]);
            gx[2] = fmaf(w, xA.z, gx[2]); gx[3] = fmaf(w, xA.w, gx[3]);
            gx[4] = fmaf(w, xB.x, gx[4]); gx[5] = fmaf(w, xB.y, gx[5]);
            gx[6] = fmaf(w, xB.z, gx[6]); gx[7] = fmaf(w, xB.w, gx[7]);
        }
        #pragma unroll 4
        for (int k = 0; k < 128; k++) {
            float w = wp[(size_t)k*384];
            float4 hA = *(const float4*)(h_s + k*8);
            float4 hB = *(const float4*)(h_s + k*8 + 4);
            acc[0] = fmaf(w, hA.x, acc[0]); acc[1] = fmaf(w, hA.y, acc[1]);
            acc[2] = fmaf(w, hA.z, acc[2]); acc[3] = fmaf(w, hA.w, acc[3]);
            acc[4] = fmaf(w, hB.x, acc[4]); acc[5] = fmaf(w, hB.y, acc[5]);
            acc[6] = fmaf(w, hB.z, acc[6]); acc[7] = fmaf(w, hB.w, acc[7]);
        }
        if (g < 128) {
            #pragma unroll
            for (int b = 0; b < 8; b++) sA[g*8 + b] = gx[b] + acc[b] + bhh_g;
        } else if (g < 256) {
            #pragma unroll
            for (int b = 0; b < 8; b++) sB[(g-128)*8 + b] = gx[b] + acc[b] + bhh_g;
        } else {
            #pragma unroll
            for (int b = 0; b < 8; b++) { sXn[(g-256)*8 + b] = gx[b]; sHn[(g-256)*8 + b] = acc[b] + bhh_g; }
        }
        __syncthreads();
        float hnew[8];
        if (g < 128) {
            float s1[8], s2[8];
            #pragma unroll
            for (int b = 0; b < 8; b++) {
                float r  = sigm(sA[g*8 + b]);
                float z  = sigm(sB[g*8 + b]);
                float nn = tanhf(sXn[g*8 + b] + r*sHn[g*8 + b]);
                float hv = (1.f - z)*nn + z*h_s[g*8 + b];
                hnew[b] = hv; h_s[g*8 + b] = hv;
                s1[b] = hv; s2[b] = hv*hv;
            }
            #pragma unroll
            for (int off = 16; off > 0; off >>= 1) {
                #pragma unroll
                for (int b = 0; b < 8; b++) {
                    s1[b] += __shfl_down_sync(0xffffffffu, s1[b], off);
                    s2[b] += __shfl_down_sync(0xffffffffu, s2[b], off);
                }
            }
            if ((g & 31) == 0) { int w = g >> 5;
                #pragma unroll
                for (int b = 0; b < 8; b++) { red1[w*8 + b] = s1[b]; red2[w*8 + b] = s2[b]; }
            }
        }
        __syncthreads();
        if (g < 128) {
            #pragma unroll
            for (int b = 0; b < 8; b++) {
                float mean = (red1[b] + red1[8+b] + red1[16+b] + red1[24+b]) * 0.0078125f;
                float msq  = (red2[b] + red2[8+b] + red2[16+b] + red2[24+b]) * 0.0078125f;
                float var  = msq - mean*mean;
                float rstd = rsqrtf(var + 1e-5f);
                int bm = (bg*8 + b)*16 + n;
                g_Hc[((size_t)bm*256 + t)*136 + g] = (hnew[b] - mean)*rstd*lg[g] + lb[g];
            }
        } else if (g < 136) {
            float uv = g_utab[t*8 + (g - 128)];
            #pragma unroll
            for (int b = 0; b < 8; b++) {
                int bm = (bg*8 + b)*16 + n;
                g_Hc[((size_t)bm*256 + t)*136 + g] = uv;
            }
        }
        __syncthreads();
    }
}

// ---------------- K3: P = Hc @ Wcat^T   (262144 x 136) @ (136 x 256) ----------------
__global__ void __launch_bounds__(256) k3_gemm_hc()
{
    const int KD = 136;
    __shared__ float As[1024], Bs[1024];
    int tid = threadIdx.x;
    size_t row0 = (size_t)blockIdx.x*128; int col0 = blockIdx.y*128;
    int lr = tid >> 1, lq = (tid & 1)*4;
    const float* Ag = g_Hc + (row0 + lr)*KD + lq;
    const float* Bg = g_Wcat + (size_t)(col0 + lr)*KD + lq;
    float acc[8][8];
    #pragma unroll
    for (int i = 0; i < 8; i++) {
        #pragma unroll
        for (int j = 0; j < 8; j++) acc[i][j] = 0.f;
    }
    int tr = tid >> 4, tc = tid & 15;
    for (int k0 = 0; k0 < KD; k0 += 8) {
        float4 a4 = *(const float4*)(Ag + k0);
        float4 b4 = *(const float4*)(Bg + k0);
        As[(lq+0)*128 + lr] = a4.x; As[(lq+1)*128 + lr] = a4.y;
        As[(lq+2)*128 + lr] = a4.z; As[(lq+3)*128 + lr] = a4.w;
        Bs[(lq+0)*128 + lr] = b4.x; Bs[(lq+1)*128 + lr] = b4.y;
        Bs[(lq+2)*128 + lr] = b4.z; Bs[(lq+3)*128 + lr] = b4.w;
        __syncthreads();
        #pragma unroll
        for (int kk = 0; kk < 8; kk++) {
            float af[8], bf[8];
            *(float4*)(af)   = *(const float4*)(As + kk*128 + tr*8);
            *(float4*)(af+4) = *(const float4*)(As + kk*128 + tr*8 + 4);
            *(float4*)(bf)   = *(const float4*)(Bs + kk*128 + tc*8);
            *(float4*)(bf+4) = *(const float4*)(Bs + kk*128 + tc*8 + 4);
            #pragma unroll
            for (int i = 0; i < 8; i++)
                #pragma unroll
                for (int j = 0; j < 8; j++) acc[i][j] = fmaf(af[i], bf[j], acc[i][j]);
        }
        __syncthreads();
    }
    #pragma unroll
    for (int i = 0; i < 8; i++) {
        size_t row = row0 + tr*8 + i;
        float* cp = g_P + row*256 + col0 + tc*8;
        *(float4*)cp     = make_float4(acc[i][0], acc[i][1], acc[i][2], acc[i][3]);
        *(float4*)(cp+4) = make_float4(acc[i][4], acc[i][5], acc[i][6], acc[i][7]);
    }
}

// ---------------- K4: graph mix + self + leaky -> Z ----------------
__global__ void __launch_bounds__(256) k4_mix(const int* __restrict__ phases)
{
    __shared__ float Am[256], sP[2048];
    int tid = threadIdx.x; int b = blockIdx.y; int t0 = blockIdx.x*8;
    Am[tid] = g_Aph[phases[b]*256 + tid];
    for (int tc = 0; tc < 8; tc++) {
        int t = t0 + tc;
        __syncthreads();
        for (int idx = tid; idx < 2048; idx += 256) { int j = idx >> 7, d = idx & 127;
            sP[idx] = g_P[((size_t)(b*16 + j)*256 + t)*256 + d]; }
        __syncthreads();
        for (int idx = tid; idx < 2048; idx += 256) {
            int i = idx >> 7, d = idx & 127;
            size_t row = (size_t)(b*16 + i)*256 + t;
            float accv = g_P[row*256 + 128 + d];
            #pragma unroll
            for (int j = 0; j < 16; j++) accv = fmaf(Am[i*16 + j], sP[j*128 + d], accv);
            g_Z[row*128 + d] = (accv >= 0.f) ? accv : 0.1f*accv;
        }
    }
}

// ---------------- K5: K|V = Z @ Wkv^T ; K fp16 [m][d][t], V fp16 [m][t][d] ----------------
__global__ void __launch_bounds__(256) k5_gemm_kv()
{
    const int KD = 128;
    __shared__ float As[1024], Bs[1024];
    int tid = threadIdx.x;
    size_t row0 = (size_t)blockIdx.x*128; int col0 = blockIdx.y*128;
    int lr = tid >> 1, lq = (tid & 1)*4;
    const float* Ag = g_Z + (row0 + lr)*KD + lq;
    const float* Bg = g_Wkv + (size_t)(col0 + lr)*KD + lq;
    float acc[8][8];
    #pragma unroll
    for (int i = 0; i < 8; i++) {
        #pragma unroll
        for (int j = 0; j < 8; j++) acc[i][j] = 0.f;
    }
    int tr = tid >> 4, tc = tid & 15;
    for (int k0 = 0; k0 < KD; k0 += 8) {
        float4 a4 = *(const float4*)(Ag + k0);
        float4 b4 = *(const float4*)(Bg + k0);
        As[(lq+0)*128 + lr] = a4.x; As[(lq+1)*128 + lr] = a4.y;
        As[(lq+2)*128 + lr] = a4.z; As[(lq+3)*128 + lr] = a4.w;
        Bs[(lq+0)*128 + lr] = b4.x; Bs[(lq+1)*128 + lr] = b4.y;
        Bs[(lq+2)*128 + lr] = b4.z; Bs[(lq+3)*128 + lr] = b4.w;
        __syncthreads();
        #pragma unroll
        for (int kk = 0; kk < 8; kk++) {
            float af[8], bf[8];
            *(float4*)(af)   = *(const float4*)(As + kk*128 + tr*8);
            *(float4*)(af+4) = *(const float4*)(As + kk*128 + tr*8 + 4);
            *(float4*)(bf)   = *(const float4*)(Bs + kk*128 + tc*8);
            *(float4*)(bf+4) = *(const float4*)(Bs + kk*128 + tc*8 + 4);
            #pragma unroll
            for (int i = 0; i < 8; i++)
                #pragma unroll
                for (int j = 0; j < 8; j++) acc[i][j] = fmaf(af[i], bf[j], acc[i][j]);
        }
        __syncthreads();
    }
    #pragma unroll
    for (int i = 0; i < 8; i++) {
        int row = (int)row0 + tr*8 + i;
        int m = row >> 8, t = row & 255;
        if (col0 == 0) { // K half: transpose store fp16 [m][d][t]
            #pragma unroll
            for (int j = 0; j < 8; j++)
                g_K[(size_t)m*32768 + (size_t)(tc*8 + j)*256 + t] = __float2half(acc[i][j]);
        } else {         // V half: fp16 [m][t][d]
            __half2* vp = (__half2*)(g_V + (size_t)row*128 + tc*8);
            vp[0] = __floats2half2_rn(acc[i][0], acc[i][1]);
            vp[1] = __floats2half2_rn(acc[i][2], acc[i][3]);
            vp[2] = __floats2half2_rn(acc[i][4], acc[i][5]);
            vp[3] = __floats2half2_rn(acc[i][6], acc[i][7]);
        }
    }
}

// ---------------- K6: decode init ----------------
__global__ void k6_init()
{
    int i = blockIdx.x*256 + threadIdx.x;
    if (i < 1024*128) { int m = i >> 7, d = i & 127;
        g_h[i] = g_Z[((size_t)m*256 + 255)*128 + d]; }
    if (i < 1024*16) { g_yA[i] = 0.f; g_yB[i] = 0.f; }
}

// ---------------- D12: fused y-mix + attention + GRU cell + readout (ping-pong y) ----------------
__global__ void __launch_bounds__(384) d12_step(const int* __restrict__ phases,
                                                const float* __restrict__ X,
                                                const float* __restrict__ cbih,
                                                const float* __restrict__ cbhh,
                                                const float* __restrict__ readW,
                                                const float* __restrict__ readb,
                                                float* __restrict__ out, int step)
{
    __shared__ float ys[256], h_s[128], sc[256], red[256], cp[256], arow[16];
    __shared__ float inp[144], sA[128], sB[128], sXn[128], sHn[128], hn_s[128];
    const float* y_in  = (step & 1) ? g_yB : g_yA;
    float*       y_out = (step & 1) ? g_yA : g_yB;
    int tid = threadIdx.x; int m = blockIdx.x; int b = m >> 4, n = m & 15;
    if (tid < 256) ys[tid] = y_in[b*256 + tid];
    if (tid < 16) arow[tid] = g_Aph[phases[b]*256 + n*16 + tid];
    if (tid >= 256) h_s[tid - 256] = g_h[m*128 + (tid - 256)];
    __syncthreads();
    // y-mix -> inp[128..143]
    if (tid < 16) {
        float a = 0.f;
        #pragma unroll
        for (int j = 0; j < 16; j++) a = fmaf(arow[j], ys[j*16 + tid], a);
        inp[128 + tid] = ys[n*16 + tid] + 0.3f*a;
    }
    // scores over t (256 threads), K fp16 [m][d][t]
    float s = 0.f;
    if (tid < 256) {
        const __half* kp = g_K + (size_t)m*32768 + tid;
        float acc = 0.f;
        #pragma unroll 8
        for (int d = 0; d < 128; d++) acc = fmaf(__half2float(kp[(size_t)d*256]), h_s[d], acc);
        s = acc * g_scale[0];
        red[tid] = s;
    }
    __syncthreads();
    for (int o = 128; o > 0; o >>= 1) { if (tid < o) red[tid] = fmaxf(red[tid], red[tid+o]); __syncthreads(); }
    float mx = red[0]; __syncthreads();
    float e = 0.f;
    if (tid < 256) { e = expf(s - mx); red[tid] = e; }
    __syncthreads();
    for (int o = 128; o > 0; o >>= 1) { if (tid < o) red[tid] += red[tid+o]; __syncthreads(); }
    if (tid < 256) sc[tid] = e * (1.0f / red[0]);
    __syncthreads();
    // ctx: 256 threads, each (half,d), V fp16 [m][t][d]
    if (tid < 256) {
        int d = tid & 127, half = tid >> 7;
        const __half* vp = g_V + ((size_t)m*256 + half*128)*128 + d;
        float accv = 0.f;
        #pragma unroll 8
        for (int tt = 0; tt < 128; tt++) accv = fmaf(sc[half*128 + tt], __half2float(vp[(size_t)tt*128]), accv);
        cp[tid] = accv;
    }
    __syncthreads();
    if (tid < 128) inp[tid] = cp[tid] + cp[tid + 128];
    __syncthreads();
    // GRU cell: all 384 threads compute one gate pre-activation
    int g = tid;
    float gx = cbih[g], gh = cbhh[g];
    const float* wi = g_cWihT + g;
    #pragma unroll 8
    for (int k = 0; k < 144; k++) gx = fmaf(wi[(size_t)k*384], inp[k], gx);
    const float* wh = g_cWhhT + g;
    #pragma unroll 8
    for (int k = 0; k < 128; k++) gh = fmaf(wh[(size_t)k*384], h_s[k], gh);
    if (g < 128) sA[g] = gx + gh;
    else if (g < 256) sB[g - 128] = gx + gh;
    else { sXn[g - 256] = gx; sHn[g - 256] = gh; }
    __syncthreads();
    if (g < 128) {
        float r  = sigm(sA[g]);
        float z  = sigm(sB[g]);
        float nn = tanhf(sXn[g] + r*sHn[g]);
        float hv = (1.f - z)*nn + z*h_s[g];
        g_h[m*128 + g] = hv; hn_s[g] = hv;
    }
    __syncthreads();
    if (g < 128) {
        int c = g >> 3, r8 = g & 7;
        const float* rw = readW + c*128 + r8*16;
        const float* hp = hn_s + r8*16;
        float a = 0.f;
        #pragma unroll
        for (int i = 0; i < 16; i++) a = fmaf(rw[i], hp[i], a);
        a += __shfl_down_sync(0xffffffffu, a, 4, 8);
        a += __shfl_down_sync(0xffffffffu, a, 2, 8);
        a += __shfl_down_sync(0xffffffffu, a, 1, 8);
        if (r8 == 0) {
            float yt = a + readb[c] + inp[128 + c];
            y_out[m*16 + c] = yt;
            float vv = X[(size_t)(m*16 + c)*256 + 255] + yt;
            out[(m*16 + c)*32 + step] = vv;
            if (step == 0) out[524288 + m*16 + c] = vv;
        }
    }
}

// ---------------- host launch ----------------
extern "C" void kernel_launch(void* const* d_in, const int* in_sizes, int n_in,
                              void* d_out, int out_size)
{
    const float* X      = (const float*)d_in[0];
    const int*   phases = (const int*)  d_in[1];
    const float* gWih   = (const float*)d_in[2];
    const float* gWhh   = (const float*)d_in[3];
    const float* gbih   = (const float*)d_in[4];
    const float* gbhh   = (const float*)d_in[5];
    const float* lng    = (const float*)d_in[6];
    const float* lnb    = (const float*)d_in[7];
    const float* tW     = (const float*)d_in[8];
    const float* tb     = (const float*)d_in[9];
    const float* S      = (const float*)d_in[10];
    const float* G      = (const float*)d_in[11];
    const float* Wself  = (const float*)d_in[12];
    const float* Wneigh = (const float*)d_in[13];
    const float* cWih   = (const float*)d_in[14];
    const float* cWhh   = (const float*)d_in[15];
    const float* cbih   = (const float*)d_in[16];
    const float* cbhh   = (const float*)d_in[17];
    const float* readW  = (const float*)d_in[18];
    const float* readb  = (const float*)d_in[19];
    const float* Wk     = (const float*)d_in[20];
    const float* Wv     = (const float*)d_in[21];
    const float* ltau   = (const float*)d_in[22];
    float* out = (float*)d_out;

    const int k2_smem = K2_SMEM_FLOATS * (int)sizeof(float);
    cudaFuncSetAttribute(k2_gru, cudaFuncAttributeMaxDynamicSharedMemorySize, k2_smem);

    k0_prep<<<1, 256>>>(Wneigh, Wself, Wk, Wv, S, G, tW, tb, ltau);
    {
        int total = 16*384*128 + 384*144 + 384*128;
        k_trans<<<(total + 255)/256, 256>>>(gWhh, cWih, cWhh);
    }
    k2_gru<<<128, 384, k2_smem>>>(X, gWih, gbih, gbhh, lng, lnb);
    k3_gemm_hc<<<dim3(2048, 2), 256>>>();
    k4_mix<<<dim3(32, 64), 256>>>(phases);
    k5_gemm_kv<<<dim3(2048, 2), 256>>>();
    k6_init<<<512, 256>>>();
    for (int s = 0; s < 32; s++) {
        d12_step<<<1024, 384>>>(phases, X, cbih, cbhh, readW, readb, out, s);
    }
    (void)in_sizes; (void)n_in; (void)out_size;
}

// round 8
// speedup vs baseline: 1.0374x; 1.0298x over previous
#include <cuda_runtime.h>
#include <cuda_fp16.h>
#include <cstdint>

// ---------------- problem constants ----------------
// B=64 N=16 C=16 T=256 DH=128 DT=8 DP=128 TOUT=32 P=4 DIN=136

// ---------------- scratch (static device arrays; no allocation) ----------------
__device__ float g_Hc [64u*16u*256u*136u];   // [bm*T+t][136]  142MB
__device__ float g_P  [64u*16u*256u*256u];   // [row][0:128]=Hc*Wn^T, [128:256]=Hc*Wself^T
__device__ float g_Z  [64u*16u*256u*128u];   // [row][128]
__device__ __half g_K [1024u*128u*256u];     // [m][d][t]  fp16 (transposed for decoder)
__device__ __half g_V [1024u*256u*128u];     // [m][t][d]  fp16
__device__ float g_WhhT [16*128*384];        // [n][k][g]
__device__ float g_Wcat [256*136];           // rows 0..127 = Wn (spectral-normed), 128..255 = W_self
__device__ float g_Wkv  [256*128];           // rows 0..127 = Wk, 128..255 = Wv
__device__ float g_cWihT[144*384];           // [k][g]
__device__ float g_cWhhT[128*384];           // [k][g]
__device__ float g_Aph  [4*16*16];           // per-phase graph
__device__ float g_utab [256*8];             // tanh(t*tW+tb)
__device__ float g_h   [1024*128];
__device__ float g_yA  [1024*16];            // ping-pong y state
__device__ float g_yB  [1024*16];
__device__ float g_ctx [1024*128];
__device__ float g_ymix[1024*16];
__device__ float g_scale[1];

__device__ __forceinline__ float sigm(float x){ return 1.0f/(1.0f+expf(-x)); }

// ---------------- K0: spectral norm, phase graphs, u table, weight packs ----------------
__global__ void __launch_bounds__(256) k0_prep(
    const float* __restrict__ Wneigh, const float* __restrict__ Wself,
    const float* __restrict__ Wk, const float* __restrict__ Wv,
    const float* __restrict__ S, const float* __restrict__ G,
    const float* __restrict__ tW, const float* __restrict__ tb,
    const float* __restrict__ ltau)
{
    __shared__ float u[128], v[136], red[256], sig;
    int tid = threadIdx.x;
    if (tid < 128) u[tid] = 1.0f / sqrtf(128.0f);
    __syncthreads();
    for (int it = 0; it < 15; it++) {
        float vv = 0.f;
        if (tid < 136) { float s = 0.f; for (int i = 0; i < 128; i++) s += Wneigh[i*136+tid]*u[i]; vv = s; }
        red[tid] = (tid < 136) ? vv*vv : 0.f; __syncthreads();
        for (int o = 128; o > 0; o >>= 1) { if (tid < o) red[tid] += red[tid+o]; __syncthreads(); }
        float nv = sqrtf(red[0]); __syncthreads();
        if (tid < 136) v[tid] = vv / nv;
        __syncthreads();
        float uu = 0.f;
        if (tid < 128) { float s = 0.f; for (int j = 0; j < 136; j++) s += Wneigh[tid*136+j]*v[j]; uu = s; }
        red[tid] = (tid < 128) ? uu*uu : 0.f; __syncthreads();
        for (int o = 128; o > 0; o >>= 1) { if (tid < o) red[tid] += red[tid+o]; __syncthreads(); }
        float nu = sqrtf(red[0]); __syncthreads();
        if (tid < 128) u[tid] = uu / nu;
        __syncthreads();
    }
    {
        float p = 0.f;
        if (tid < 128) { float s = 0.f; for (int j = 0; j < 136; j++) s += Wneigh[tid*136+j]*v[j]; p = u[tid]*s; }
        red[tid] = p; __syncthreads();
        for (int o = 128; o > 0; o >>= 1) { if (tid < o) red[tid] += red[tid+o]; __syncthreads(); }
        if (tid == 0) sig = red[0];
        __syncthreads();
    }
    float inv = 1.0f / sig;
    for (int i = tid; i < 128*136; i += 256) { g_Wcat[i] = Wneigh[i]*inv; g_Wcat[17408+i] = Wself[i]; }
    for (int i = tid; i < 128*128; i += 256) { g_Wkv[i] = Wk[i]; g_Wkv[16384+i] = Wv[i]; }
    for (int i = tid; i < 256*8;   i += 256) { int t = i >> 3, j = i & 7;
        g_utab[i] = tanhf(((float)t * (1.0f/255.0f)) * tW[j] + tb[j]); }
    if (tid == 0) g_scale[0] = expf(ltau[0]);
    if (tid < 4) {
        int p = tid; float gg[16]; float gs = 0.f;
        for (int i = 0; i < 16; i++) { float x = G[p*16+i]; float sp = log1pf(expf(x)) + 1e-6f; gg[i] = sp; gs += sp; }
        float gn = 16.0f / fmaxf(gs, 1e-6f);
        for (int i = 0; i < 16; i++) {
            float den = 0.f;
            for (int j = 0; j < 16; j++) { float sv = (i==j) ? 0.f : S[p*256+i*16+j]; den += fabsf(sv); }
            den = fmaxf(den, 1e-6f);
            float gi = gg[i]*gn;
            for (int j = 0; j < 16; j++) { float sv = (i==j) ? 0.f : S[p*256+i*16+j];
                g_Aph[p*256+i*16+j] = sv/den*gi; }
        }
    }
}

// ---------------- weight transposes ----------------
__global__ void k_trans(const float* __restrict__ Whh,
                        const float* __restrict__ cWih, const float* __restrict__ cWhh)
{
    int i = blockIdx.x*256 + threadIdx.x;
    const int T1 = 16*384*128, T2 = 384*144, T3 = 384*128;
    if (i < T1) {
        int n = i / 49152, r = i % 49152, gg = r / 128, k = r % 128;
        g_WhhT[n*49152 + k*384 + gg] = Whh[i];
    } else if (i < T1 + T2) {
        int j = i - T1; int gg = j / 144, k = j % 144;
        g_cWihT[k*384 + gg] = cWih[j];
    } else if (i < T1 + T2 + T3) {
        int j = i - T1 - T2; int gg = j / 128, k = j % 128;
        g_cWhhT[k*384 + gg] = cWhh[j];
    }
}

// ---------------- K2: GRU scan over T with fused Gx compute + LN, writes Hc ----------------
#define K2_SMEM_FLOATS 19776
__global__ void __launch_bounds__(384) k2_gru(const float* __restrict__ X,
                                              const float* __restrict__ Wih,
                                              const float* __restrict__ bih,
                                              const float* __restrict__ bhh,
                                              const float* __restrict__ lng,
                                              const float* __restrict__ lnb)
{
    extern __shared__ float sm[];
    float* h_s   = sm;
    float* sA    = sm + 1024;
    float* sB    = sm + 2048;
    float* sXn   = sm + 3072;
    float* sHn   = sm + 4096;
    float* Wih_s = sm + 5120;
    float* Xs    = sm + 11264;
    float* lg    = sm + 19456;
    float* lb    = sm + 19584;
    float* red1  = sm + 19712;
    float* red2  = sm + 19744;

    int g = threadIdx.x;
    int n = blockIdx.x >> 3, bg = blockIdx.x & 7;
    if (g < 128) { lg[g] = lng[g]; lb[g] = lnb[g]; }
    for (int i = g; i < 1024; i += 384) h_s[i] = 0.f;
    for (int i = g; i < 6144; i += 384) { int g2 = i >> 4, c = i & 15;
        Wih_s[c*384 + g2] = Wih[n*6144 + i]; }
    float bhh_g = bhh[n*384 + g];
    float bih_g = bih[n*384 + g];
    const float* wp = g_WhhT + n*49152 + g;
    __syncthreads();

    for (int t = 0; t < 256; t++) {
        int tc = t & 63;
        if (tc == 0) {
            __syncthreads();
            for (int i = g; i < 8192; i += 384) {
                int b = i >> 10, r = i & 1023, c = r >> 6, tcc = r & 63;
                Xs[c*512 + tcc*8 + b] = X[(size_t)((bg*8 + b)*16 + n)*4096 + c*256 + t + tcc];
            }
            __syncthreads();
        }
        float acc[8], gx[8];
        #pragma unroll
        for (int b = 0; b < 8; b++) { acc[b] = 0.f; gx[b] = bih_g; }
        #pragma unroll
        for (int c = 0; c < 16; c++) {
            float w = Wih_s[c*384 + g];
            float4 xA = *(const float4*)(Xs + c*512 + tc*8);
            float4 xB = *(const float4*)(Xs + c*512 + tc*8 + 4);
            gx[0] = fmaf(w, xA.x, gx[0]); gx[1] = fmaf(w, xA.y, gx[1]);
            gx[2] = fmaf(w, xA.z, gx[2]); gx[3] = fmaf(w, xA.w, gx[3]);
            gx[4] = fmaf(w, xB.x, gx[4]); gx[5] = fmaf(w, xB.y, gx[5]);
            gx[6] = fmaf(w, xB.z, gx[6]); gx[7] = fmaf(w, xB.w, gx[7]);
        }
        #pragma unroll 4
        for (int k = 0; k < 128; k++) {
            float w = wp[(size_t)k*384];
            float4 hA = *(const float4*)(h_s + k*8);
            float4 hB = *(const float4*)(h_s + k*8 + 4);
            acc[0] = fmaf(w, hA.x, acc[0]); acc[1] = fmaf(w, hA.y, acc[1]);
            acc[2] = fmaf(w, hA.z, acc[2]); acc[3] = fmaf(w, hA.w, acc[3]);
            acc[4] = fmaf(w, hB.x, acc[4]); acc[5] = fmaf(w, hB.y, acc[5]);
            acc[6] = fmaf(w, hB.z, acc[6]); acc[7] = fmaf(w, hB.w, acc[7]);
        }
        if (g < 128) {
            #pragma unroll
            for (int b = 0; b < 8; b++) sA[g*8 + b] = gx[b] + acc[b] + bhh_g;
        } else if (g < 256) {
            #pragma unroll
            for (int b = 0; b < 8; b++) sB[(g-128)*8 + b] = gx[b] + acc[b] + bhh_g;
        } else {
            #pragma unroll
            for (int b = 0; b < 8; b++) { sXn[(g-256)*8 + b] = gx[b]; sHn[(g-256)*8 + b] = acc[b] + bhh_g; }
        }
        __syncthreads();
        float hnew[8];
        if (g < 128) {
            float s1[8], s2[8];
            #pragma unroll
            for (int b = 0; b < 8; b++) {
                float r  = sigm(sA[g*8 + b]);
                float z  = sigm(sB[g*8 + b]);
                float nn = tanhf(sXn[g*8 + b] + r*sHn[g*8 + b]);
                float hv = (1.f - z)*nn + z*h_s[g*8 + b];
                hnew[b] = hv; h_s[g*8 + b] = hv;
                s1[b] = hv; s2[b] = hv*hv;
            }
            #pragma unroll
            for (int off = 16; off > 0; off >>= 1) {
                #pragma unroll
                for (int b = 0; b < 8; b++) {
                    s1[b] += __shfl_down_sync(0xffffffffu, s1[b], off);
                    s2[b] += __shfl_down_sync(0xffffffffu, s2[b], off);
                }
            }
            if ((g & 31) == 0) { int w = g >> 5;
                #pragma unroll
                for (int b = 0; b < 8; b++) { red1[w*8 + b] = s1[b]; red2[w*8 + b] = s2[b]; }
            }
        }
        __syncthreads();
        if (g < 128) {
            #pragma unroll
            for (int b = 0; b < 8; b++) {
                float mean = (red1[b] + red1[8+b] + red1[16+b] + red1[24+b]) * 0.0078125f;
                float msq  = (red2[b] + red2[8+b] + red2[16+b] + red2[24+b]) * 0.0078125f;
                float var  = msq - mean*mean;
                float rstd = rsqrtf(var + 1e-5f);
                int bm = (bg*8 + b)*16 + n;
                g_Hc[((size_t)bm*256 + t)*136 + g] = (hnew[b] - mean)*rstd*lg[g] + lb[g];
            }
        } else if (g < 136) {
            float uv = g_utab[t*8 + (g - 128)];
            #pragma unroll
            for (int b = 0; b < 8; b++) {
                int bm = (bg*8 + b)*16 + n;
                g_Hc[((size_t)bm*256 + t)*136 + g] = uv;
            }
        }
        __syncthreads();
    }
}

// ---------------- K3: P = Hc @ Wcat^T   (262144 x 136) @ (136 x 256) ----------------
__global__ void __launch_bounds__(256) k3_gemm_hc()
{
    const int KD = 136;
    __shared__ float As[1024], Bs[1024];
    int tid = threadIdx.x;
    size_t row0 = (size_t)blockIdx.x*128; int col0 = blockIdx.y*128;
    int lr = tid >> 1, lq = (tid & 1)*4;
    const float* Ag = g_Hc + (row0 + lr)*KD + lq;
    const float* Bg = g_Wcat + (size_t)(col0 + lr)*KD + lq;
    float acc[8][8];
    #pragma unroll
    for (int i = 0; i < 8; i++) {
        #pragma unroll
        for (int j = 0; j < 8; j++) acc[i][j] = 0.f;
    }
    int tr = tid >> 4, tc = tid & 15;
    for (int k0 = 0; k0 < KD; k0 += 8) {
        float4 a4 = *(const float4*)(Ag + k0);
        float4 b4 = *(const float4*)(Bg + k0);
        As[(lq+0)*128 + lr] = a4.x; As[(lq+1)*128 + lr] = a4.y;
        As[(lq+2)*128 + lr] = a4.z; As[(lq+3)*128 + lr] = a4.w;
        Bs[(lq+0)*128 + lr] = b4.x; Bs[(lq+1)*128 + lr] = b4.y;
        Bs[(lq+2)*128 + lr] = b4.z; Bs[(lq+3)*128 + lr] = b4.w;
        __syncthreads();
        #pragma unroll
        for (int kk = 0; kk < 8; kk++) {
            float af[8], bf[8];
            *(float4*)(af)   = *(const float4*)(As + kk*128 + tr*8);
            *(float4*)(af+4) = *(const float4*)(As + kk*128 + tr*8 + 4);
            *(float4*)(bf)   = *(const float4*)(Bs + kk*128 + tc*8);
            *(float4*)(bf+4) = *(const float4*)(Bs + kk*128 + tc*8 + 4);
            #pragma unroll
            for (int i = 0; i < 8; i++)
                #pragma unroll
                for (int j = 0; j < 8; j++) acc[i][j] = fmaf(af[i], bf[j], acc[i][j]);
        }
        __syncthreads();
    }
    #pragma unroll
    for (int i = 0; i < 8; i++) {
        size_t row = row0 + tr*8 + i;
        float* cp = g_P + row*256 + col0 + tc*8;
        *(float4*)cp     = make_float4(acc[i][0], acc[i][1], acc[i][2], acc[i][3]);
        *(float4*)(cp+4) = make_float4(acc[i][4], acc[i][5], acc[i][6], acc[i][7]);
    }
}

// ---------------- K4: graph mix + self + leaky -> Z ----------------
__global__ void __launch_bounds__(256) k4_mix(const int* __restrict__ phases)
{
    __shared__ float Am[256], sP[2048];
    int tid = threadIdx.x; int b = blockIdx.y; int t0 = blockIdx.x*8;
    Am[tid] = g_Aph[phases[b]*256 + tid];
    for (int tc = 0; tc < 8; tc++) {
        int t = t0 + tc;
        __syncthreads();
        for (int idx = tid; idx < 2048; idx += 256) { int j = idx >> 7, d = idx & 127;
            sP[idx] = g_P[((size_t)(b*16 + j)*256 + t)*256 + d]; }
        __syncthreads();
        for (int idx = tid; idx < 2048; idx += 256) {
            int i = idx >> 7, d = idx & 127;
            size_t row = (size_t)(b*16 + i)*256 + t;
            float accv = g_P[row*256 + 128 + d];
            #pragma unroll
            for (int j = 0; j < 16; j++) accv = fmaf(Am[i*16 + j], sP[j*128 + d], accv);
            g_Z[row*128 + d] = (accv >= 0.f) ? accv : 0.1f*accv;
        }
    }
}

// ---------------- K5: K|V = Z @ Wkv^T ; K fp16 [m][d][t], V fp16 [m][t][d] ----------------
__global__ void __launch_bounds__(256) k5_gemm_kv()
{
    const int KD = 128;
    __shared__ float As[1024], Bs[1024];
    int tid = threadIdx.x;
    size_t row0 = (size_t)blockIdx.x*128; int col0 = blockIdx.y*128;
    int lr = tid >> 1, lq = (tid & 1)*4;
    const float* Ag = g_Z + (row0 + lr)*KD + lq;
    const float* Bg = g_Wkv + (size_t)(col0 + lr)*KD + lq;
    float acc[8][8];
    #pragma unroll
    for (int i = 0; i < 8; i++) {
        #pragma unroll
        for (int j = 0; j < 8; j++) acc[i][j] = 0.f;
    }
    int tr = tid >> 4, tc = tid & 15;
    for (int k0 = 0; k0 < KD; k0 += 8) {
        float4 a4 = *(const float4*)(Ag + k0);
        float4 b4 = *(const float4*)(Bg + k0);
        As[(lq+0)*128 + lr] = a4.x; As[(lq+1)*128 + lr] = a4.y;
        As[(lq+2)*128 + lr] = a4.z; As[(lq+3)*128 + lr] = a4.w;
        Bs[(lq+0)*128 + lr] = b4.x; Bs[(lq+1)*128 + lr] = b4.y;
        Bs[(lq+2)*128 + lr] = b4.z; Bs[(lq+3)*128 + lr] = b4.w;
        __syncthreads();
        #pragma unroll
        for (int kk = 0; kk < 8; kk++) {
            float af[8], bf[8];
            *(float4*)(af)   = *(const float4*)(As + kk*128 + tr*8);
            *(float4*)(af+4) = *(const float4*)(As + kk*128 + tr*8 + 4);
            *(float4*)(bf)   = *(const float4*)(Bs + kk*128 + tc*8);
            *(float4*)(bf+4) = *(const float4*)(Bs + kk*128 + tc*8 + 4);
            #pragma unroll
            for (int i = 0; i < 8; i++)
                #pragma unroll
                for (int j = 0; j < 8; j++) acc[i][j] = fmaf(af[i], bf[j], acc[i][j]);
        }
        __syncthreads();
    }
    #pragma unroll
    for (int i = 0; i < 8; i++) {
        int row = (int)row0 + tr*8 + i;
        int m = row >> 8, t = row & 255;
        if (col0 == 0) { // K half: transpose store fp16 [m][d][t]
            #pragma unroll
            for (int j = 0; j < 8; j++)
                g_K[(size_t)m*32768 + (size_t)(tc*8 + j)*256 + t] = __float2half(acc[i][j]);
        } else {         // V half: fp16 [m][t][d]
            __half2* vp = (__half2*)(g_V + (size_t)row*128 + tc*8);
            vp[0] = __floats2half2_rn(acc[i][0], acc[i][1]);
            vp[1] = __floats2half2_rn(acc[i][2], acc[i][3]);
            vp[2] = __floats2half2_rn(acc[i][4], acc[i][5]);
            vp[3] = __floats2half2_rn(acc[i][6], acc[i][7]);
        }
    }
}

// ---------------- K6: decode init ----------------
__global__ void k6_init()
{
    int i = blockIdx.x*256 + threadIdx.x;
    if (i < 1024*128) { int m = i >> 7, d = i & 127;
        g_h[i] = g_Z[((size_t)m*256 + 255)*128 + d]; }
    if (i < 1024*16) { g_yA[i] = 0.f; g_yB[i] = 0.f; }
}

// ---------------- D-S1: y-mix + attention -> g_ctx, g_ymix ----------------
__global__ void __launch_bounds__(256) d_s1(const int* __restrict__ phases, int step)
{
    __shared__ float ys[256], h_s[128], sc[256], arow[16], wred[8];
    int tid = threadIdx.x; int m = blockIdx.x; int b = m >> 4, n = m & 15;
    const float* y_in = (step & 1) ? g_yB : g_yA;
    ys[tid] = y_in[b*256 + tid];
    if (tid < 16) arow[tid] = g_Aph[phases[b]*256 + n*16 + tid];
    if (tid < 128) h_s[tid] = g_h[m*128 + tid];
    __syncthreads();
    if (tid < 16) {
        float a = 0.f;
        #pragma unroll
        for (int j = 0; j < 16; j++) a = fmaf(arow[j], ys[j*16 + tid], a);
        g_ymix[m*16 + tid] = ys[n*16 + tid] + 0.3f*a;
    }
    // scores over t=tid, K fp16 [m][d][t]
    const __half* kp = g_K + (size_t)m*32768 + tid;
    float s = 0.f;
    #pragma unroll 8
    for (int d = 0; d < 128; d++) s = fmaf(__half2float(kp[(size_t)d*256]), h_s[d], s);
    s *= g_scale[0];
    // shuffle-based softmax (3 barriers)
    int lane = tid & 31, wid = tid >> 5;
    float wm = s;
    #pragma unroll
    for (int o = 16; o > 0; o >>= 1) wm = fmaxf(wm, __shfl_xor_sync(0xffffffffu, wm, o));
    if (lane == 0) wred[wid] = wm;
    __syncthreads();
    float mx = wred[0];
    #pragma unroll
    for (int w = 1; w < 8; w++) mx = fmaxf(mx, wred[w]);
    float e = expf(s - mx);
    float wsum = e;
    #pragma unroll
    for (int o = 16; o > 0; o >>= 1) wsum += __shfl_xor_sync(0xffffffffu, wsum, o);
    __syncthreads();
    if (lane == 0) wred[wid] = wsum;
    __syncthreads();
    float tot = 0.f;
    #pragma unroll
    for (int w = 0; w < 8; w++) tot += wred[w];
    sc[tid] = e * (1.0f / tot);
    __syncthreads();
    // ctx: thread = (half, d), V fp16 [m][t][d]
    int d = tid & 127, half = tid >> 7;
    const __half* vp = g_V + ((size_t)m*256 + half*128)*128 + d;
    float accv = 0.f;
    #pragma unroll 8
    for (int tt = 0; tt < 128; tt++) accv = fmaf(sc[half*128 + tt], __half2float(vp[(size_t)tt*128]), accv);
    // combine two halves via smem (reuse ys)
    __syncthreads();
    ys[tid] = accv;
    __syncthreads();
    if (tid < 128) g_ctx[m*128 + tid] = ys[tid] + ys[tid + 128];
}

// ---------------- D-S2: tiled GRU cell + readout (8 m per block) ----------------
__global__ void __launch_bounds__(384) d_s2(const float* __restrict__ X,
                                            const float* __restrict__ cbih,
                                            const float* __restrict__ cbhh,
                                            const float* __restrict__ readW,
                                            const float* __restrict__ readb,
                                            float* __restrict__ out, int step)
{
    __shared__ float inA[144*8];   // [k][mm]  k<128: ctx, 128..143: ymix
    __shared__ float hS [128*8];   // [k][mm]
    __shared__ float sA[128*8], sB[128*8], sXn[128*8], sHn[128*8], hn[128*8];
    int tid = threadIdx.x; int m0 = blockIdx.x * 8;
    float* y_out = (step & 1) ? g_yA : g_yB;

    for (int i = tid; i < 144*8; i += 384) {
        int mm = i & 7, k = i >> 3;
        inA[i] = (k < 128) ? g_ctx[(m0 + mm)*128 + k] : g_ymix[(m0 + mm)*16 + (k - 128)];
    }
    for (int i = tid; i < 128*8; i += 384) {
        int mm = i & 7, k = i >> 3;
        hS[i] = g_h[(m0 + mm)*128 + k];
    }
    __syncthreads();

    int g = tid;
    float gxv[8], ghv[8];
    {
        float bi = cbih[g], bh = cbhh[g];
        #pragma unroll
        for (int mm = 0; mm < 8; mm++) { gxv[mm] = bi; ghv[mm] = bh; }
    }
    const float* wi = g_cWihT + g;
    #pragma unroll 4
    for (int k = 0; k < 144; k++) {
        float w = wi[(size_t)k*384];
        float4 a = *(const float4*)(inA + k*8);
        float4 b2 = *(const float4*)(inA + k*8 + 4);
        gxv[0] = fmaf(w, a.x, gxv[0]); gxv[1] = fmaf(w, a.y, gxv[1]);
        gxv[2] = fmaf(w, a.z, gxv[2]); gxv[3] = fmaf(w, a.w, gxv[3]);
        gxv[4] = fmaf(w, b2.x, gxv[4]); gxv[5] = fmaf(w, b2.y, gxv[5]);
        gxv[6] = fmaf(w, b2.z, gxv[6]); gxv[7] = fmaf(w, b2.w, gxv[7]);
    }
    const float* wh = g_cWhhT + g;
    #pragma unroll 4
    for (int k = 0; k < 128; k++) {
        float w = wh[(size_t)k*384];
        float4 a = *(const float4*)(hS + k*8);
        float4 b2 = *(const float4*)(hS + k*8 + 4);
        ghv[0] = fmaf(w, a.x, ghv[0]); ghv[1] = fmaf(w, a.y, ghv[1]);
        ghv[2] = fmaf(w, a.z, ghv[2]); ghv[3] = fmaf(w, a.w, ghv[3]);
        ghv[4] = fmaf(w, b2.x, ghv[4]); ghv[5] = fmaf(w, b2.y, ghv[5]);
        ghv[6] = fmaf(w, b2.z, ghv[6]); ghv[7] = fmaf(w, b2.w, ghv[7]);
    }
    if (g < 128) {
        #pragma unroll
        for (int mm = 0; mm < 8; mm++) sA[g*8 + mm] = gxv[mm] + ghv[mm];
    } else if (g < 256) {
        #pragma unroll
        for (int mm = 0; mm < 8; mm++) sB[(g-128)*8 + mm] = gxv[mm] + ghv[mm];
    } else {
        #pragma unroll
        for (int mm = 0; mm < 8; mm++) { sXn[(g-256)*8 + mm] = gxv[mm]; sHn[(g-256)*8 + mm] = ghv[mm]; }
    }
    __syncthreads();
    if (g < 128) {
        #pragma unroll
        for (int mm = 0; mm < 8; mm++) {
            float r  = sigm(sA[g*8 + mm]);
            float z  = sigm(sB[g*8 + mm]);
            float nn = tanhf(sXn[g*8 + mm] + r*sHn[g*8 + mm]);
            float hv = (1.f - z)*nn + z*hS[g*8 + mm];
            g_h[(m0 + mm)*128 + g] = hv;
            hn[g*8 + mm] = hv;
        }
    }
    __syncthreads();
    if (g < 128) {
        int c = g >> 3, r8 = g & 7;
        float a[8];
        #pragma unroll
        for (int mm = 0; mm < 8; mm++) a[mm] = 0.f;
        const float* rw = readW + c*128 + r8*16;
        #pragma unroll
        for (int i = 0; i < 16; i++) {
            float w = rw[i];
            const float* hp = hn + (r8*16 + i)*8;
            #pragma unroll
            for (int mm = 0; mm < 8; mm++) a[mm] = fmaf(w, hp[mm], a[mm]);
        }
        #pragma unroll
        for (int mm = 0; mm < 8; mm++) {
            a[mm] += __shfl_down_sync(0xffffffffu, a[mm], 4, 8);
            a[mm] += __shfl_down_sync(0xffffffffu, a[mm], 2, 8);
            a[mm] += __shfl_down_sync(0xffffffffu, a[mm], 1, 8);
        }
        if (r8 == 0) {
            float rb = readb[c];
            #pragma unroll
            for (int mm = 0; mm < 8; mm++) {
                int mc = (m0 + mm)*16 + c;
                float yt = a[mm] + rb + inA[(128 + c)*8 + mm];
                y_out[mc] = yt;
                float vv = X[(size_t)mc*256 + 255] + yt;
                out[mc*32 + step] = vv;
                if (step == 0) out[524288 + mc] = vv;
            }
        }
    }
}

// ---------------- host launch ----------------
extern "C" void kernel_launch(void* const* d_in, const int* in_sizes, int n_in,
                              void* d_out, int out_size)
{
    const float* X      = (const float*)d_in[0];
    const int*   phases = (const int*)  d_in[1];
    const float* gWih   = (const float*)d_in[2];
    const float* gWhh   = (const float*)d_in[3];
    const float* gbih   = (const float*)d_in[4];
    const float* gbhh   = (const float*)d_in[5];
    const float* lng    = (const float*)d_in[6];
    const float* lnb    = (const float*)d_in[7];
    const float* tW     = (const float*)d_in[8];
    const float* tb     = (const float*)d_in[9];
    const float* S      = (const float*)d_in[10];
    const float* G      = (const float*)d_in[11];
    const float* Wself  = (const float*)d_in[12];
    const float* Wneigh = (const float*)d_in[13];
    const float* cWih   = (const float*)d_in[14];
    const float* cWhh   = (const float*)d_in[15];
    const float* cbih   = (const float*)d_in[16];
    const float* cbhh   = (const float*)d_in[17];
    const float* readW  = (const float*)d_in[18];
    const float* readb  = (const float*)d_in[19];
    const float* Wk     = (const float*)d_in[20];
    const float* Wv     = (const float*)d_in[21];
    const float* ltau   = (const float*)d_in[22];
    float* out = (float*)d_out;

    const int k2_smem = K2_SMEM_FLOATS * (int)sizeof(float);
    cudaFuncSetAttribute(k2_gru, cudaFuncAttributeMaxDynamicSharedMemorySize, k2_smem);

    k0_prep<<<1, 256>>>(Wneigh, Wself, Wk, Wv, S, G, tW, tb, ltau);
    {
        int total = 16*384*128 + 384*144 + 384*128;
        k_trans<<<(total + 255)/256, 256>>>(gWhh, cWih, cWhh);
    }
    k2_gru<<<128, 384, k2_smem>>>(X, gWih, gbih, gbhh, lng, lnb);
    k3_gemm_hc<<<dim3(2048, 2), 256>>>();
    k4_mix<<<dim3(32, 64), 256>>>(phases);
    k5_gemm_kv<<<dim3(2048, 2), 256>>>();
    k6_init<<<512, 256>>>();
    for (int s = 0; s < 32; s++) {
        d_s1<<<1024, 256>>>(phases, s);
        d_s2<<<128, 384>>>(X, cbih, cbhh, readW, readb, out, s);
    }
    (void)in_sizes; (void)n_in; (void)out_size;
}

// round 9
// speedup vs baseline: 1.1422x; 1.1010x over previous
#include <cuda_runtime.h>
#include <cuda_fp16.h>
#include <cstdint>

// ---------------- problem constants ----------------
// B=64 N=16 C=16 T=256 DH=128 DT=8 DP=128 TOUT=32 P=4 DIN=136

// ---------------- scratch (static device arrays; no allocation) ----------------
__device__ __half g_Hc [64u*16u*256u*144u];  // [row][144] fp16, cols 136..143 = 0  (75MB)
__device__ __half g_P  [64u*16u*256u*256u];  // [row][0:128]=Hc*Wn^T, [128:256]=Hc*Wself^T (134MB)
__device__ __half g_Z  [64u*16u*256u*128u];  // [row][128] fp16 (67MB)
__device__ __half g_K [1024u*128u*256u];     // [m][d][t]  fp16
__device__ __half g_V [1024u*256u*128u];     // [m][t][d]  fp16
__device__ float g_WhhT [16*128*384];        // [n][k][g]
__device__ __half g_WcatH[256*144];          // rows 0..127 = Wn/sigma, 128..255 = W_self (K padded)
__device__ __half g_WkvH [256*128];          // rows 0..127 = Wk, 128..255 = Wv
__device__ float g_cWihT[144*384];           // [k][g]
__device__ float g_cWhhT[128*384];           // [k][g]
__device__ float g_Aph  [4*16*16];           // per-phase graph
__device__ float g_utab [256*8];             // tanh(t*tW+tb)
__device__ float g_h   [1024*128];
__device__ float g_yA  [1024*16];            // ping-pong y state
__device__ float g_yB  [1024*16];
__device__ float g_ctx [1024*128];
__device__ float g_ymix[1024*16];
__device__ float g_scale[1];

__device__ __forceinline__ float sigm(float x){ return 1.0f/(1.0f+expf(-x)); }

__device__ __forceinline__ void mma16816(float* c, const uint32_t* a, const uint32_t* b) {
    asm volatile("mma.sync.aligned.m16n8k16.row.col.f32.f16.f16.f32 "
        "{%0,%1,%2,%3}, {%4,%5,%6,%7}, {%8,%9}, {%0,%1,%2,%3};"
        : "+f"(c[0]), "+f"(c[1]), "+f"(c[2]), "+f"(c[3])
        : "r"(a[0]), "r"(a[1]), "r"(a[2]), "r"(a[3]), "r"(b[0]), "r"(b[1]));
}

// ---------------- K0: spectral norm, phase graphs, u table, weight packs ----------------
__global__ void __launch_bounds__(256) k0_prep(
    const float* __restrict__ Wneigh, const float* __restrict__ Wself,
    const float* __restrict__ Wk, const float* __restrict__ Wv,
    const float* __restrict__ S, const float* __restrict__ G,
    const float* __restrict__ tW, const float* __restrict__ tb,
    const float* __restrict__ ltau)
{
    __shared__ float u[128], v[136], red[256], sig;
    int tid = threadIdx.x;
    if (tid < 128) u[tid] = 1.0f / sqrtf(128.0f);
    __syncthreads();
    for (int it = 0; it < 15; it++) {
        float vv = 0.f;
        if (tid < 136) { float s = 0.f; for (int i = 0; i < 128; i++) s += Wneigh[i*136+tid]*u[i]; vv = s; }
        red[tid] = (tid < 136) ? vv*vv : 0.f; __syncthreads();
        for (int o = 128; o > 0; o >>= 1) { if (tid < o) red[tid] += red[tid+o]; __syncthreads(); }
        float nv = sqrtf(red[0]); __syncthreads();
        if (tid < 136) v[tid] = vv / nv;
        __syncthreads();
        float uu = 0.f;
        if (tid < 128) { float s = 0.f; for (int j = 0; j < 136; j++) s += Wneigh[tid*136+j]*v[j]; uu = s; }
        red[tid] = (tid < 128) ? uu*uu : 0.f; __syncthreads();
        for (int o = 128; o > 0; o >>= 1) { if (tid < o) red[tid] += red[tid+o]; __syncthreads(); }
        float nu = sqrtf(red[0]); __syncthreads();
        if (tid < 128) u[tid] = uu / nu;
        __syncthreads();
    }
    {
        float p = 0.f;
        if (tid < 128) { float s = 0.f; for (int j = 0; j < 136; j++) s += Wneigh[tid*136+j]*v[j]; p = u[tid]*s; }
        red[tid] = p; __syncthreads();
        for (int o = 128; o > 0; o >>= 1) { if (tid < o) red[tid] += red[tid+o]; __syncthreads(); }
        if (tid == 0) sig = red[0];
        __syncthreads();
    }
    float inv = 1.0f / sig;
    for (int i = tid; i < 128*144; i += 256) {
        int r = i / 144, cidx = i % 144;
        float wn_ = (cidx < 136) ? Wneigh[r*136 + cidx]*inv : 0.f;
        float ws_ = (cidx < 136) ? Wself[r*136 + cidx] : 0.f;
        g_WcatH[i] = __float2half(wn_);
        g_WcatH[128*144 + i] = __float2half(ws_);
    }
    for (int i = tid; i < 128*128; i += 256) {
        g_WkvH[i] = __float2half(Wk[i]);
        g_WkvH[16384 + i] = __float2half(Wv[i]);
    }
    for (int i = tid; i < 256*8;   i += 256) { int t = i >> 3, j = i & 7;
        g_utab[i] = tanhf(((float)t * (1.0f/255.0f)) * tW[j] + tb[j]); }
    if (tid == 0) g_scale[0] = expf(ltau[0]);
    if (tid < 4) {
        int p = tid; float gg[16]; float gs = 0.f;
        for (int i = 0; i < 16; i++) { float x = G[p*16+i]; float sp = log1pf(expf(x)) + 1e-6f; gg[i] = sp; gs += sp; }
        float gn = 16.0f / fmaxf(gs, 1e-6f);
        for (int i = 0; i < 16; i++) {
            float den = 0.f;
            for (int j = 0; j < 16; j++) { float sv = (i==j) ? 0.f : S[p*256+i*16+j]; den += fabsf(sv); }
            den = fmaxf(den, 1e-6f);
            float gi = gg[i]*gn;
            for (int j = 0; j < 16; j++) { float sv = (i==j) ? 0.f : S[p*256+i*16+j];
                g_Aph[p*256+i*16+j] = sv/den*gi; }
        }
    }
}

// ---------------- weight transposes ----------------
__global__ void k_trans(const float* __restrict__ Whh,
                        const float* __restrict__ cWih, const float* __restrict__ cWhh)
{
    int i = blockIdx.x*256 + threadIdx.x;
    const int T1 = 16*384*128, T2 = 384*144, T3 = 384*128;
    if (i < T1) {
        int n = i / 49152, r = i % 49152, gg = r / 128, k = r % 128;
        g_WhhT[n*49152 + k*384 + gg] = Whh[i];
    } else if (i < T1 + T2) {
        int j = i - T1; int gg = j / 144, k = j % 144;
        g_cWihT[k*384 + gg] = cWih[j];
    } else if (i < T1 + T2 + T3) {
        int j = i - T1 - T2; int gg = j / 128, k = j % 128;
        g_cWhhT[k*384 + gg] = cWhh[j];
    }
}

// ---------------- K2: GRU scan over T with fused Gx compute + LN, writes Hc (fp16) ----------------
#define K2_SMEM_FLOATS 19776
__global__ void __launch_bounds__(384) k2_gru(const float* __restrict__ X,
                                              const float* __restrict__ Wih,
                                              const float* __restrict__ bih,
                                              const float* __restrict__ bhh,
                                              const float* __restrict__ lng,
                                              const float* __restrict__ lnb)
{
    extern __shared__ float sm[];
    float* h_s   = sm;
    float* sA    = sm + 1024;
    float* sB    = sm + 2048;
    float* sXn   = sm + 3072;
    float* sHn   = sm + 4096;
    float* Wih_s = sm + 5120;
    float* Xs    = sm + 11264;
    float* lg    = sm + 19456;
    float* lb    = sm + 19584;
    float* red1  = sm + 19712;
    float* red2  = sm + 19744;

    int g = threadIdx.x;
    int n = blockIdx.x >> 3, bg = blockIdx.x & 7;
    if (g < 128) { lg[g] = lng[g]; lb[g] = lnb[g]; }
    for (int i = g; i < 1024; i += 384) h_s[i] = 0.f;
    for (int i = g; i < 6144; i += 384) { int g2 = i >> 4, c = i & 15;
        Wih_s[c*384 + g2] = Wih[n*6144 + i]; }
    float bhh_g = bhh[n*384 + g];
    float bih_g = bih[n*384 + g];
    const float* wp = g_WhhT + n*49152 + g;
    __syncthreads();

    for (int t = 0; t < 256; t++) {
        int tc = t & 63;
        if (tc == 0) {
            __syncthreads();
            for (int i = g; i < 8192; i += 384) {
                int b = i >> 10, r = i & 1023, c = r >> 6, tcc = r & 63;
                Xs[c*512 + tcc*8 + b] = X[(size_t)((bg*8 + b)*16 + n)*4096 + c*256 + t + tcc];
            }
            __syncthreads();
        }
        float acc[8], gx[8];
        #pragma unroll
        for (int b = 0; b < 8; b++) { acc[b] = 0.f; gx[b] = bih_g; }
        #pragma unroll
        for (int c = 0; c < 16; c++) {
            float w = Wih_s[c*384 + g];
            float4 xA = *(const float4*)(Xs + c*512 + tc*8);
            float4 xB = *(const float4*)(Xs + c*512 + tc*8 + 4);
            gx[0] = fmaf(w, xA.x, gx[0]); gx[1] = fmaf(w, xA.y, gx[1]);
            gx[2] = fmaf(w, xA.z, gx[2]); gx[3] = fmaf(w, xA.w, gx[3]);
            gx[4] = fmaf(w, xB.x, gx[4]); gx[5] = fmaf(w, xB.y, gx[5]);
            gx[6] = fmaf(w, xB.z, gx[6]); gx[7] = fmaf(w, xB.w, gx[7]);
        }
        #pragma unroll 4
        for (int k = 0; k < 128; k++) {
            float w = wp[(size_t)k*384];
            float4 hA = *(const float4*)(h_s + k*8);
            float4 hB = *(const float4*)(h_s + k*8 + 4);
            acc[0] = fmaf(w, hA.x, acc[0]); acc[1] = fmaf(w, hA.y, acc[1]);
            acc[2] = fmaf(w, hA.z, acc[2]); acc[3] = fmaf(w, hA.w, acc[3]);
            acc[4] = fmaf(w, hB.x, acc[4]); acc[5] = fmaf(w, hB.y, acc[5]);
            acc[6] = fmaf(w, hB.z, acc[6]); acc[7] = fmaf(w, hB.w, acc[7]);
        }
        if (g < 128) {
            #pragma unroll
            for (int b = 0; b < 8; b++) sA[g*8 + b] = gx[b] + acc[b] + bhh_g;
        } else if (g < 256) {
            #pragma unroll
            for (int b = 0; b < 8; b++) sB[(g-128)*8 + b] = gx[b] + acc[b] + bhh_g;
        } else {
            #pragma unroll
            for (int b = 0; b < 8; b++) { sXn[(g-256)*8 + b] = gx[b]; sHn[(g-256)*8 + b] = acc[b] + bhh_g; }
        }
        __syncthreads();
        float hnew[8];
        if (g < 128) {
            float s1[8], s2[8];
            #pragma unroll
            for (int b = 0; b < 8; b++) {
                float r  = sigm(sA[g*8 + b]);
                float z  = sigm(sB[g*8 + b]);
                float nn = tanhf(sXn[g*8 + b] + r*sHn[g*8 + b]);
                float hv = (1.f - z)*nn + z*h_s[g*8 + b];
                hnew[b] = hv; h_s[g*8 + b] = hv;
                s1[b] = hv; s2[b] = hv*hv;
            }
            #pragma unroll
            for (int off = 16; off > 0; off >>= 1) {
                #pragma unroll
                for (int b = 0; b < 8; b++) {
                    s1[b] += __shfl_down_sync(0xffffffffu, s1[b], off);
                    s2[b] += __shfl_down_sync(0xffffffffu, s2[b], off);
                }
            }
            if ((g & 31) == 0) { int w = g >> 5;
                #pragma unroll
                for (int b = 0; b < 8; b++) { red1[w*8 + b] = s1[b]; red2[w*8 + b] = s2[b]; }
            }
        }
        __syncthreads();
        if (g < 128) {
            #pragma unroll
            for (int b = 0; b < 8; b++) {
                float mean = (red1[b] + red1[8+b] + red1[16+b] + red1[24+b]) * 0.0078125f;
                float msq  = (red2[b] + red2[8+b] + red2[16+b] + red2[24+b]) * 0.0078125f;
                float var  = msq - mean*mean;
                float rstd = rsqrtf(var + 1e-5f);
                int bm = (bg*8 + b)*16 + n;
                g_Hc[((size_t)bm*256 + t)*144 + g] = __float2half((hnew[b] - mean)*rstd*lg[g] + lb[g]);
            }
        } else if (g < 136) {
            float uv = g_utab[t*8 + (g - 128)];
            #pragma unroll
            for (int b = 0; b < 8; b++) {
                int bm = (bg*8 + b)*16 + n;
                g_Hc[((size_t)bm*256 + t)*144 + g] = __float2half(uv);
            }
        } else if (g < 144) {
            #pragma unroll
            for (int b = 0; b < 8; b++) {
                int bm = (bg*8 + b)*16 + n;
                g_Hc[((size_t)bm*256 + t)*144 + g] = __float2half(0.f);
            }
        }
        __syncthreads();
    }
}

// ---------------- K3: P = Hc @ Wcat^T via HMMA  (262144 x 144) @ (144 x 256) ----------------
// smem: A tile 128x144 (pitch 168 halfs), B tile same -> 86016 bytes
__global__ void __launch_bounds__(256) k3_hgemm()
{
    extern __shared__ __half smh[];
    const int PITCH = 168;
    __half* As = smh;
    __half* Bs = smh + 128*PITCH;
    int tid = threadIdx.x;
    size_t row0 = (size_t)blockIdx.x * 128;
    int col0 = blockIdx.y * 128;
    for (int i = tid; i < 128*18; i += 256) {
        int r = i / 18, c = i % 18;
        *(int4*)(As + r*PITCH + c*8) = *(const int4*)(g_Hc + (row0 + r)*144 + c*8);
    }
    for (int i = tid; i < 128*18; i += 256) {
        int r = i / 18, c = i % 18;
        *(int4*)(Bs + r*PITCH + c*8) = *(const int4*)(g_WcatH + (size_t)(col0 + r)*144 + c*8);
    }
    __syncthreads();
    int w = tid >> 5, l = tid & 31;
    int wm = w & 1, wn = w >> 1;        // warp: rows 64*wm..+63, cols 32*wn..+31
    int lr = l >> 2, lk = (l & 3)*2;
    float c[4][4][4];
    #pragma unroll
    for (int mi = 0; mi < 4; mi++)
        #pragma unroll
        for (int ni = 0; ni < 4; ni++)
            #pragma unroll
            for (int q = 0; q < 4; q++) c[mi][ni][q] = 0.f;
    #pragma unroll
    for (int kc = 0; kc < 9; kc++) {
        int k0 = kc*16;
        uint32_t a[4][4], b[4][2];
        #pragma unroll
        for (int mi = 0; mi < 4; mi++) {
            const __half* ap = As + (wm*64 + mi*16 + lr)*PITCH + k0 + lk;
            a[mi][0] = *(const uint32_t*)(ap);
            a[mi][1] = *(const uint32_t*)(ap + 8*PITCH);
            a[mi][2] = *(const uint32_t*)(ap + 8);
            a[mi][3] = *(const uint32_t*)(ap + 8*PITCH + 8);
        }
        #pragma unroll
        for (int ni = 0; ni < 4; ni++) {
            const __half* bp = Bs + (wn*32 + ni*8 + lr)*PITCH + k0 + lk;
            b[ni][0] = *(const uint32_t*)(bp);
            b[ni][1] = *(const uint32_t*)(bp + 8);
        }
        #pragma unroll
        for (int mi = 0; mi < 4; mi++)
            #pragma unroll
            for (int ni = 0; ni < 4; ni++)
                mma16816(c[mi][ni], a[mi], b[ni]);
    }
    #pragma unroll
    for (int mi = 0; mi < 4; mi++) {
        size_t ra = row0 + wm*64 + mi*16 + lr;
        #pragma unroll
        for (int ni = 0; ni < 4; ni++) {
            int cc = col0 + wn*32 + ni*8 + lk;
            *(__half2*)(g_P + ra*256 + cc)     = __floats2half2_rn(c[mi][ni][0], c[mi][ni][1]);
            *(__half2*)(g_P + (ra+8)*256 + cc) = __floats2half2_rn(c[mi][ni][2], c[mi][ni][3]);
        }
    }
}

// ---------------- K4: graph mix + self + leaky -> Z (fp16 IO) ----------------
__global__ void __launch_bounds__(256) k4_mix(const int* __restrict__ phases)
{
    __shared__ float Am[256], sP[2048];
    int tid = threadIdx.x; int b = blockIdx.y; int t0 = blockIdx.x*8;
    Am[tid] = g_Aph[phases[b]*256 + tid];
    for (int tc = 0; tc < 8; tc++) {
        int t = t0 + tc;
        __syncthreads();
        for (int idx = tid; idx < 2048; idx += 256) { int j = idx >> 7, d = idx & 127;
            sP[idx] = __half2float(g_P[((size_t)(b*16 + j)*256 + t)*256 + d]); }
        __syncthreads();
        for (int idx = tid; idx < 2048; idx += 256) {
            int i = idx >> 7, d = idx & 127;
            size_t row = (size_t)(b*16 + i)*256 + t;
            float accv = __half2float(g_P[row*256 + 128 + d]);
            #pragma unroll
            for (int j = 0; j < 16; j++) accv = fmaf(Am[i*16 + j], sP[j*128 + d], accv);
            g_Z[row*128 + d] = __float2half((accv >= 0.f) ? accv : 0.1f*accv);
        }
    }
}

// ---------------- K5: K|V = Z @ Wkv^T via HMMA; K fp16 [m][d][t], V fp16 [m][t][d] ----------------
// smem: 2 x 128x128 (pitch 136 halfs) -> 69632 bytes
__global__ void __launch_bounds__(256) k5_hgemm()
{
    extern __shared__ __half smh[];
    const int PITCH = 136;
    __half* As = smh;
    __half* Bs = smh + 128*PITCH;
    int tid = threadIdx.x;
    size_t row0 = (size_t)blockIdx.x * 128;
    int col0 = blockIdx.y * 128;
    for (int i = tid; i < 128*16; i += 256) {
        int r = i >> 4, c = i & 15;
        *(int4*)(As + r*PITCH + c*8) = *(const int4*)(g_Z + (row0 + r)*128 + c*8);
    }
    for (int i = tid; i < 128*16; i += 256) {
        int r = i >> 4, c = i & 15;
        *(int4*)(Bs + r*PITCH + c*8) = *(const int4*)(g_WkvH + (size_t)(col0 + r)*128 + c*8);
    }
    __syncthreads();
    int w = tid >> 5, l = tid & 31;
    int wm = w & 1, wn = w >> 1;
    int lr = l >> 2, lk = (l & 3)*2;
    float c[4][4][4];
    #pragma unroll
    for (int mi = 0; mi < 4; mi++)
        #pragma unroll
        for (int ni = 0; ni < 4; ni++)
            #pragma unroll
            for (int q = 0; q < 4; q++) c[mi][ni][q] = 0.f;
    #pragma unroll
    for (int kc = 0; kc < 8; kc++) {
        int k0 = kc*16;
        uint32_t a[4][4], b[4][2];
        #pragma unroll
        for (int mi = 0; mi < 4; mi++) {
            const __half* ap = As + (wm*64 + mi*16 + lr)*PITCH + k0 + lk;
            a[mi][0] = *(const uint32_t*)(ap);
            a[mi][1] = *(const uint32_t*)(ap + 8*PITCH);
            a[mi][2] = *(const uint32_t*)(ap + 8);
            a[mi][3] = *(const uint32_t*)(ap + 8*PITCH + 8);
        }
        #pragma unroll
        for (int ni = 0; ni < 4; ni++) {
            const __half* bp = Bs + (wn*32 + ni*8 + lr)*PITCH + k0 + lk;
            b[ni][0] = *(const uint32_t*)(bp);
            b[ni][1] = *(const uint32_t*)(bp + 8);
        }
        #pragma unroll
        for (int mi = 0; mi < 4; mi++)
            #pragma unroll
            for (int ni = 0; ni < 4; ni++)
                mma16816(c[mi][ni], a[mi], b[ni]);
    }
    // epilogue: block covers rows of ONE m (row0 multiple of 128 -> fixed m), t = row & 255
    #pragma unroll
    for (int mi = 0; mi < 4; mi++) {
        size_t ra = row0 + wm*64 + mi*16 + lr;
        size_t rb = ra + 8;
        int ma = (int)(ra >> 8), ta = (int)(ra & 255);
        int tb2 = (int)(rb & 255);
        #pragma unroll
        for (int ni = 0; ni < 4; ni++) {
            int cc = wn*32 + ni*8 + lk;      // 0..127 within the half
            if (blockIdx.y == 0) {            // K: [m][d][t]
                __half* kb = g_K + (size_t)ma*32768;
                kb[(size_t)cc*256 + ta]     = __float2half(c[mi][ni][0]);
                kb[(size_t)(cc+1)*256 + ta] = __float2half(c[mi][ni][1]);
                kb[(size_t)cc*256 + tb2]     = __float2half(c[mi][ni][2]);
                kb[(size_t)(cc+1)*256 + tb2] = __float2half(c[mi][ni][3]);
            } else {                          // V: [row][d]
                *(__half2*)(g_V + ra*128 + cc) = __floats2half2_rn(c[mi][ni][0], c[mi][ni][1]);
                *(__half2*)(g_V + rb*128 + cc) = __floats2half2_rn(c[mi][ni][2], c[mi][ni][3]);
            }
        }
    }
}

// ---------------- K6: decode init ----------------
__global__ void k6_init()
{
    int i = blockIdx.x*256 + threadIdx.x;
    if (i < 1024*128) { int m = i >> 7, d = i & 127;
        g_h[i] = __half2float(g_Z[((size_t)m*256 + 255)*128 + d]); }
    if (i < 1024*16) { g_yA[i] = 0.f; g_yB[i] = 0.f; }
}

// ---------------- D-S1: y-mix + attention -> g_ctx, g_ymix ----------------
__global__ void __launch_bounds__(256) d_s1(const int* __restrict__ phases, int step)
{
    __shared__ float ys[256], h_s[128], sc[256], arow[16], wred[8];
    int tid = threadIdx.x; int m = blockIdx.x; int b = m >> 4, n = m & 15;
    const float* y_in = (step & 1) ? g_yB : g_yA;
    ys[tid] = y_in[b*256 + tid];
    if (tid < 16) arow[tid] = g_Aph[phases[b]*256 + n*16 + tid];
    if (tid < 128) h_s[tid] = g_h[m*128 + tid];
    __syncthreads();
    if (tid < 16) {
        float a = 0.f;
        #pragma unroll
        for (int j = 0; j < 16; j++) a = fmaf(arow[j], ys[j*16 + tid], a);
        g_ymix[m*16 + tid] = ys[n*16 + tid] + 0.3f*a;
    }
    const __half* kp = g_K + (size_t)m*32768 + tid;
    float s = 0.f;
    #pragma unroll 8
    for (int d = 0; d < 128; d++) s = fmaf(__half2float(kp[(size_t)d*256]), h_s[d], s);
    s *= g_scale[0];
    int lane = tid & 31, wid = tid >> 5;
    float wm = s;
    #pragma unroll
    for (int o = 16; o > 0; o >>= 1) wm = fmaxf(wm, __shfl_xor_sync(0xffffffffu, wm, o));
    if (lane == 0) wred[wid] = wm;
    __syncthreads();
    float mx = wred[0];
    #pragma unroll
    for (int w = 1; w < 8; w++) mx = fmaxf(mx, wred[w]);
    float e = expf(s - mx);
    float wsum = e;
    #pragma unroll
    for (int o = 16; o > 0; o >>= 1) wsum += __shfl_xor_sync(0xffffffffu, wsum, o);
    __syncthreads();
    if (lane == 0) wred[wid] = wsum;
    __syncthreads();
    float tot = 0.f;
    #pragma unroll
    for (int w = 0; w < 8; w++) tot += wred[w];
    sc[tid] = e * (1.0f / tot);
    __syncthreads();
    int d = tid & 127, half = tid >> 7;
    const __half* vp = g_V + ((size_t)m*256 + half*128)*128 + d;
    float accv = 0.f;
    #pragma unroll 8
    for (int tt = 0; tt < 128; tt++) accv = fmaf(sc[half*128 + tt], __half2float(vp[(size_t)tt*128]), accv);
    __syncthreads();
    ys[tid] = accv;
    __syncthreads();
    if (tid < 128) g_ctx[m*128 + tid] = ys[tid] + ys[tid + 128];
}

// ---------------- D-S2: tiled GRU cell + readout (8 m per block) ----------------
__global__ void __launch_bounds__(384) d_s2(const float* __restrict__ X,
                                            const float* __restrict__ cbih,
                                            const float* __restrict__ cbhh,
                                            const float* __restrict__ readW,
                                            const float* __restrict__ readb,
                                            float* __restrict__ out, int step)
{
    __shared__ float inA[144*8];
    __shared__ float hS [128*8];
    __shared__ float sA[128*8], sB[128*8], sXn[128*8], sHn[128*8], hn[128*8];
    int tid = threadIdx.x; int m0 = blockIdx.x * 8;
    float* y_out = (step & 1) ? g_yA : g_yB;

    for (int i = tid; i < 144*8; i += 384) {
        int mm = i & 7, k = i >> 3;
        inA[i] = (k < 128) ? g_ctx[(m0 + mm)*128 + k] : g_ymix[(m0 + mm)*16 + (k - 128)];
    }
    for (int i = tid; i < 128*8; i += 384) {
        int mm = i & 7, k = i >> 3;
        hS[i] = g_h[(m0 + mm)*128 + k];
    }
    __syncthreads();

    int g = tid;
    float gxv[8], ghv[8];
    {
        float bi = cbih[g], bh = cbhh[g];
        #pragma unroll
        for (int mm = 0; mm < 8; mm++) { gxv[mm] = bi; ghv[mm] = bh; }
    }
    const float* wi = g_cWihT + g;
    #pragma unroll 4
    for (int k = 0; k < 144; k++) {
        float w = wi[(size_t)k*384];
        float4 a = *(const float4*)(inA + k*8);
        float4 b2 = *(const float4*)(inA + k*8 + 4);
        gxv[0] = fmaf(w, a.x, gxv[0]); gxv[1] = fmaf(w, a.y, gxv[1]);
        gxv[2] = fmaf(w, a.z, gxv[2]); gxv[3] = fmaf(w, a.w, gxv[3]);
        gxv[4] = fmaf(w, b2.x, gxv[4]); gxv[5] = fmaf(w, b2.y, gxv[5]);
        gxv[6] = fmaf(w, b2.z, gxv[6]); gxv[7] = fmaf(w, b2.w, gxv[7]);
    }
    const float* wh = g_cWhhT + g;
    #pragma unroll 4
    for (int k = 0; k < 128; k++) {
        float w = wh[(size_t)k*384];
        float4 a = *(const float4*)(hS + k*8);
        float4 b2 = *(const float4*)(hS + k*8 + 4);
        ghv[0] = fmaf(w, a.x, ghv[0]); ghv[1] = fmaf(w, a.y, ghv[1]);
        ghv[2] = fmaf(w, a.z, ghv[2]); ghv[3] = fmaf(w, a.w, ghv[3]);
        ghv[4] = fmaf(w, b2.x, ghv[4]); ghv[5] = fmaf(w, b2.y, ghv[5]);
        ghv[6] = fmaf(w, b2.z, ghv[6]); ghv[7] = fmaf(w, b2.w, ghv[7]);
    }
    if (g < 128) {
        #pragma unroll
        for (int mm = 0; mm < 8; mm++) sA[g*8 + mm] = gxv[mm] + ghv[mm];
    } else if (g < 256) {
        #pragma unroll
        for (int mm = 0; mm < 8; mm++) sB[(g-128)*8 + mm] = gxv[mm] + ghv[mm];
    } else {
        #pragma unroll
        for (int mm = 0; mm < 8; mm++) { sXn[(g-256)*8 + mm] = gxv[mm]; sHn[(g-256)*8 + mm] = ghv[mm]; }
    }
    __syncthreads();
    if (g < 128) {
        #pragma unroll
        for (int mm = 0; mm < 8; mm++) {
            float r  = sigm(sA[g*8 + mm]);
            float z  = sigm(sB[g*8 + mm]);
            float nn = tanhf(sXn[g*8 + mm] + r*sHn[g*8 + mm]);
            float hv = (1.f - z)*nn + z*hS[g*8 + mm];
            g_h[(m0 + mm)*128 + g] = hv;
            hn[g*8 + mm] = hv;
        }
    }
    __syncthreads();
    if (g < 128) {
        int c = g >> 3, r8 = g & 7;
        float a[8];
        #pragma unroll
        for (int mm = 0; mm < 8; mm++) a[mm] = 0.f;
        const float* rw = readW + c*128 + r8*16;
        #pragma unroll
        for (int i = 0; i < 16; i++) {
            float w = rw[i];
            const float* hp = hn + (r8*16 + i)*8;
            #pragma unroll
            for (int mm = 0; mm < 8; mm++) a[mm] = fmaf(w, hp[mm], a[mm]);
        }
        #pragma unroll
        for (int mm = 0; mm < 8; mm++) {
            a[mm] += __shfl_down_sync(0xffffffffu, a[mm], 4, 8);
            a[mm] += __shfl_down_sync(0xffffffffu, a[mm], 2, 8);
            a[mm] += __shfl_down_sync(0xffffffffu, a[mm], 1, 8);
        }
        if (r8 == 0) {
            float rb = readb[c];
            #pragma unroll
            for (int mm = 0; mm < 8; mm++) {
                int mc = (m0 + mm)*16 + c;
                float yt = a[mm] + rb + inA[(128 + c)*8 + mm];
                y_out[mc] = yt;
                float vv = X[(size_t)mc*256 + 255] + yt;
                out[mc*32 + step] = vv;
                if (step == 0) out[524288 + mc] = vv;
            }
        }
    }
}

// ---------------- host launch ----------------
extern "C" void kernel_launch(void* const* d_in, const int* in_sizes, int n_in,
                              void* d_out, int out_size)
{
    const float* X      = (const float*)d_in[0];
    const int*   phases = (const int*)  d_in[1];
    const float* gWih   = (const float*)d_in[2];
    const float* gWhh   = (const float*)d_in[3];
    const float* gbih   = (const float*)d_in[4];
    const float* gbhh   = (const float*)d_in[5];
    const float* lng    = (const float*)d_in[6];
    const float* lnb    = (const float*)d_in[7];
    const float* tW     = (const float*)d_in[8];
    const float* tb     = (const float*)d_in[9];
    const float* S      = (const float*)d_in[10];
    const float* G      = (const float*)d_in[11];
    const float* Wself  = (const float*)d_in[12];
    const float* Wneigh = (const float*)d_in[13];
    const float* cWih   = (const float*)d_in[14];
    const float* cWhh   = (const float*)d_in[15];
    const float* cbih   = (const float*)d_in[16];
    const float* cbhh   = (const float*)d_in[17];
    const float* readW  = (const float*)d_in[18];
    const float* readb  = (const float*)d_in[19];
    const float* Wk     = (const float*)d_in[20];
    const float* Wv     = (const float*)d_in[21];
    const float* ltau   = (const float*)d_in[22];
    float* out = (float*)d_out;

    const int k2_smem = K2_SMEM_FLOATS * (int)sizeof(float);
    const int k3_smem = 2 * 128 * 168 * (int)sizeof(__half);  // 86016
    const int k5_smem = 2 * 128 * 136 * (int)sizeof(__half);  // 69632
    cudaFuncSetAttribute(k2_gru, cudaFuncAttributeMaxDynamicSharedMemorySize, k2_smem);
    cudaFuncSetAttribute(k3_hgemm, cudaFuncAttributeMaxDynamicSharedMemorySize, k3_smem);
    cudaFuncSetAttribute(k5_hgemm, cudaFuncAttributeMaxDynamicSharedMemorySize, k5_smem);

    k0_prep<<<1, 256>>>(Wneigh, Wself, Wk, Wv, S, G, tW, tb, ltau);
    {
        int total = 16*384*128 + 384*144 + 384*128;
        k_trans<<<(total + 255)/256, 256>>>(gWhh, cWih, cWhh);
    }
    k2_gru<<<128, 384, k2_smem>>>(X, gWih, gbih, gbhh, lng, lnb);
    k3_hgemm<<<dim3(2048, 2), 256, k3_smem>>>();
    k4_mix<<<dim3(32, 64), 256>>>(phases);
    k5_hgemm<<<dim3(2048, 2), 256, k5_smem>>>();
    k6_init<<<512, 256>>>();
    for (int s = 0; s < 32; s++) {
        d_s1<<<1024, 256>>>(phases, s);
        d_s2<<<128, 384>>>(X, cbih, cbhh, readW, readb, out, s);
    }
    (void)in_sizes; (void)n_in; (void)out_size;
}

// round 10
// speedup vs baseline: 1.1997x; 1.0504x over previous
#include <cuda_runtime.h>
#include <cuda_fp16.h>
#include <cstdint>

// ---------------- problem constants ----------------
// B=64 N=16 C=16 T=256 DH=128 DT=8 DP=128 TOUT=32 P=4 DIN=136

// ---------------- scratch (static device arrays; no allocation) ----------------
__device__ __half g_Hc [64u*16u*256u*144u];  // [row][144] fp16, cols 136..143 = 0
__device__ __half g_P  [64u*16u*256u*256u];  // [row][0:128]=Hc*Wn^T, [128:256]=Hc*Wself^T
__device__ __half g_Z  [64u*16u*256u*128u];  // [row][128] fp16
__device__ __half g_K [1024u*128u*256u];     // [m][d][t]  fp16
__device__ __half g_V [1024u*256u*128u];     // [m][t][d]  fp16
__device__ float g_WhhT [16*128*384];        // [n][k][g]
__device__ __half g_WcatH[256*144];          // rows 0..127 = Wn/sigma, 128..255 = W_self
__device__ __half g_WkvH [256*128];          // rows 0..127 = Wk, 128..255 = Wv
__device__ float g_cWihT[144*384];           // [k][g]
__device__ float g_cWhhT[128*384];           // [k][g]
__device__ float g_Aph  [4*16*16];
__device__ float g_utab [256*8];
__device__ float g_h   [1024*128];
__device__ float g_yA  [1024*16];
__device__ float g_yB  [1024*16];
__device__ float g_ctx [1024*128];
__device__ float g_ymix[1024*16];
__device__ float g_scale[1];

__device__ __forceinline__ float sigm(float x){ return 1.0f/(1.0f+expf(-x)); }

__device__ __forceinline__ void mma16816(float* c, const uint32_t* a, const uint32_t* b) {
    asm volatile("mma.sync.aligned.m16n8k16.row.col.f32.f16.f16.f32 "
        "{%0,%1,%2,%3}, {%4,%5,%6,%7}, {%8,%9}, {%0,%1,%2,%3};"
        : "+f"(c[0]), "+f"(c[1]), "+f"(c[2]), "+f"(c[3])
        : "r"(a[0]), "r"(a[1]), "r"(a[2]), "r"(a[3]), "r"(b[0]), "r"(b[1]));
}

// packed fp32x2 helpers
__device__ __forceinline__ unsigned long long pack2(float x) {
    unsigned long long r;
    asm("mov.b64 %0, {%1, %1};" : "=l"(r) : "f"(x));
    return r;
}
__device__ __forceinline__ void fma2(unsigned long long& acc, unsigned long long a, unsigned long long b) {
    asm("fma.rn.f32x2 %0, %1, %2, %0;" : "+l"(acc) : "l"(a), "l"(b));
}
__device__ __forceinline__ void lds_v2u64(unsigned addr, unsigned long long& lo, unsigned long long& hi) {
    asm volatile("ld.shared.v2.u64 {%0, %1}, [%2];" : "=l"(lo), "=l"(hi) : "r"(addr));
}
__device__ __forceinline__ void unpack2(unsigned long long p, float& lo, float& hi) {
    asm("mov.b64 {%0, %1}, %2;" : "=f"(lo), "=f"(hi) : "l"(p));
}

// ---------------- K0: spectral norm, phase graphs, u table, weight packs ----------------
__global__ void __launch_bounds__(256) k0_prep(
    const float* __restrict__ Wneigh, const float* __restrict__ Wself,
    const float* __restrict__ Wk, const float* __restrict__ Wv,
    const float* __restrict__ S, const float* __restrict__ G,
    const float* __restrict__ tW, const float* __restrict__ tb,
    const float* __restrict__ ltau)
{
    __shared__ float u[128], v[136], red[256], sig;
    int tid = threadIdx.x;
    if (tid < 128) u[tid] = 1.0f / sqrtf(128.0f);
    __syncthreads();
    for (int it = 0; it < 15; it++) {
        float vv = 0.f;
        if (tid < 136) { float s = 0.f; for (int i = 0; i < 128; i++) s += Wneigh[i*136+tid]*u[i]; vv = s; }
        red[tid] = (tid < 136) ? vv*vv : 0.f; __syncthreads();
        for (int o = 128; o > 0; o >>= 1) { if (tid < o) red[tid] += red[tid+o]; __syncthreads(); }
        float nv = sqrtf(red[0]); __syncthreads();
        if (tid < 136) v[tid] = vv / nv;
        __syncthreads();
        float uu = 0.f;
        if (tid < 128) { float s = 0.f; for (int j = 0; j < 136; j++) s += Wneigh[tid*136+j]*v[j]; uu = s; }
        red[tid] = (tid < 128) ? uu*uu : 0.f; __syncthreads();
        for (int o = 128; o > 0; o >>= 1) { if (tid < o) red[tid] += red[tid+o]; __syncthreads(); }
        float nu = sqrtf(red[0]); __syncthreads();
        if (tid < 128) u[tid] = uu / nu;
        __syncthreads();
    }
    {
        float p = 0.f;
        if (tid < 128) { float s = 0.f; for (int j = 0; j < 136; j++) s += Wneigh[tid*136+j]*v[j]; p = u[tid]*s; }
        red[tid] = p; __syncthreads();
        for (int o = 128; o > 0; o >>= 1) { if (tid < o) red[tid] += red[tid+o]; __syncthreads(); }
        if (tid == 0) sig = red[0];
        __syncthreads();
    }
    float inv = 1.0f / sig;
    for (int i = tid; i < 128*144; i += 256) {
        int r = i / 144, cidx = i % 144;
        float wn_ = (cidx < 136) ? Wneigh[r*136 + cidx]*inv : 0.f;
        float ws_ = (cidx < 136) ? Wself[r*136 + cidx] : 0.f;
        g_WcatH[i] = __float2half(wn_);
        g_WcatH[128*144 + i] = __float2half(ws_);
    }
    for (int i = tid; i < 128*128; i += 256) {
        g_WkvH[i] = __float2half(Wk[i]);
        g_WkvH[16384 + i] = __float2half(Wv[i]);
    }
    for (int i = tid; i < 256*8;   i += 256) { int t = i >> 3, j = i & 7;
        g_utab[i] = tanhf(((float)t * (1.0f/255.0f)) * tW[j] + tb[j]); }
    if (tid == 0) g_scale[0] = expf(ltau[0]);
    if (tid < 4) {
        int p = tid; float gg[16]; float gs = 0.f;
        for (int i = 0; i < 16; i++) { float x = G[p*16+i]; float sp = log1pf(expf(x)) + 1e-6f; gg[i] = sp; gs += sp; }
        float gn = 16.0f / fmaxf(gs, 1e-6f);
        for (int i = 0; i < 16; i++) {
            float den = 0.f;
            for (int j = 0; j < 16; j++) { float sv = (i==j) ? 0.f : S[p*256+i*16+j]; den += fabsf(sv); }
            den = fmaxf(den, 1e-6f);
            float gi = gg[i]*gn;
            for (int j = 0; j < 16; j++) { float sv = (i==j) ? 0.f : S[p*256+i*16+j];
                g_Aph[p*256+i*16+j] = sv/den*gi; }
        }
    }
}

// ---------------- weight transposes ----------------
__global__ void k_trans(const float* __restrict__ Whh,
                        const float* __restrict__ cWih, const float* __restrict__ cWhh)
{
    int i = blockIdx.x*256 + threadIdx.x;
    const int T1 = 16*384*128, T2 = 384*144, T3 = 384*128;
    if (i < T1) {
        int n = i / 49152, r = i % 49152, gg = r / 128, k = r % 128;
        g_WhhT[n*49152 + k*384 + gg] = Whh[i];
    } else if (i < T1 + T2) {
        int j = i - T1; int gg = j / 144, k = j % 144;
        g_cWihT[k*384 + gg] = cWih[j];
    } else if (i < T1 + T2 + T3) {
        int j = i - T1 - T2; int gg = j / 128, k = j % 128;
        g_cWhhT[k*384 + gg] = cWhh[j];
    }
}

// ---------------- K2: GRU scan over T with fused Gx compute + LN, writes Hc (fp16) ----------------
#define K2_SMEM_FLOATS 19776
__global__ void __launch_bounds__(384) k2_gru(const float* __restrict__ X,
                                              const float* __restrict__ Wih,
                                              const float* __restrict__ bih,
                                              const float* __restrict__ bhh,
                                              const float* __restrict__ lng,
                                              const float* __restrict__ lnb)
{
    extern __shared__ float sm[];
    float* h_s   = sm;
    float* sA    = sm + 1024;
    float* sB    = sm + 2048;
    float* sXn   = sm + 3072;
    float* sHn   = sm + 4096;
    float* Wih_s = sm + 5120;
    float* Xs    = sm + 11264;
    float* lg    = sm + 19456;
    float* lb    = sm + 19584;
    float* red1  = sm + 19712;
    float* red2  = sm + 19744;

    int g = threadIdx.x;
    int n = blockIdx.x >> 3, bg = blockIdx.x & 7;
    if (g < 128) { lg[g] = lng[g]; lb[g] = lnb[g]; }
    for (int i = g; i < 1024; i += 384) h_s[i] = 0.f;
    for (int i = g; i < 6144; i += 384) { int g2 = i >> 4, c = i & 15;
        Wih_s[c*384 + g2] = Wih[n*6144 + i]; }
    float bhh_g = bhh[n*384 + g];
    float bih_g = bih[n*384 + g];
    const float* wp = g_WhhT + n*49152 + g;
    unsigned hbase  = (unsigned)__cvta_generic_to_shared(h_s);
    unsigned xbase  = (unsigned)__cvta_generic_to_shared(Xs);
    unsigned long long bih2 = pack2(bih_g);
    __syncthreads();

    for (int t = 0; t < 256; t++) {
        int tc = t & 63;
        if (tc == 0) {
            __syncthreads();
            for (int i = g; i < 8192; i += 384) {
                int b = i >> 10, r = i & 1023, c = r >> 6, tcc = r & 63;
                Xs[c*512 + tcc*8 + b] = X[(size_t)((bg*8 + b)*16 + n)*4096 + c*256 + t + tcc];
            }
            __syncthreads();
        }
        unsigned long long a01 = 0, a23 = 0, a45 = 0, a67 = 0;
        unsigned long long g01 = bih2, g23 = bih2, g45 = bih2, g67 = bih2;
        // Gx on the fly: 16 c-iterations (packed)
        #pragma unroll
        for (int c = 0; c < 16; c++) {
            unsigned long long w2 = pack2(Wih_s[c*384 + g]);
            unsigned long long x01, x23, x45, x67;
            unsigned xaddr = xbase + (unsigned)(c*512 + tc*8) * 4u;
            lds_v2u64(xaddr, x01, x23);
            lds_v2u64(xaddr + 16u, x45, x67);
            fma2(g01, w2, x01); fma2(g23, w2, x23);
            fma2(g45, w2, x45); fma2(g67, w2, x67);
        }
        // Whh @ h (packed)
        #pragma unroll 8
        for (int k = 0; k < 128; k++) {
            unsigned long long w2 = pack2(wp[(size_t)k*384]);
            unsigned long long h01, h23, h45, h67;
            unsigned haddr = hbase + (unsigned)(k*32);
            lds_v2u64(haddr, h01, h23);
            lds_v2u64(haddr + 16u, h45, h67);
            fma2(a01, w2, h01); fma2(a23, w2, h23);
            fma2(a45, w2, h45); fma2(a67, w2, h67);
        }
        float acc[8], gx[8];
        unpack2(a01, acc[0], acc[1]); unpack2(a23, acc[2], acc[3]);
        unpack2(a45, acc[4], acc[5]); unpack2(a67, acc[6], acc[7]);
        unpack2(g01, gx[0], gx[1]);   unpack2(g23, gx[2], gx[3]);
        unpack2(g45, gx[4], gx[5]);   unpack2(g67, gx[6], gx[7]);
        if (g < 128) {
            #pragma unroll
            for (int b = 0; b < 8; b++) sA[g*8 + b] = gx[b] + acc[b] + bhh_g;
        } else if (g < 256) {
            #pragma unroll
            for (int b = 0; b < 8; b++) sB[(g-128)*8 + b] = gx[b] + acc[b] + bhh_g;
        } else {
            #pragma unroll
            for (int b = 0; b < 8; b++) { sXn[(g-256)*8 + b] = gx[b]; sHn[(g-256)*8 + b] = acc[b] + bhh_g; }
        }
        __syncthreads();
        float hnew[8];
        if (g < 128) {
            float s1[8], s2[8];
            #pragma unroll
            for (int b = 0; b < 8; b++) {
                float r  = sigm(sA[g*8 + b]);
                float z  = sigm(sB[g*8 + b]);
                float nn = tanhf(sXn[g*8 + b] + r*sHn[g*8 + b]);
                float hv = (1.f - z)*nn + z*h_s[g*8 + b];
                hnew[b] = hv; h_s[g*8 + b] = hv;
                s1[b] = hv; s2[b] = hv*hv;
            }
            #pragma unroll
            for (int off = 16; off > 0; off >>= 1) {
                #pragma unroll
                for (int b = 0; b < 8; b++) {
                    s1[b] += __shfl_down_sync(0xffffffffu, s1[b], off);
                    s2[b] += __shfl_down_sync(0xffffffffu, s2[b], off);
                }
            }
            if ((g & 31) == 0) { int w = g >> 5;
                #pragma unroll
                for (int b = 0; b < 8; b++) { red1[w*8 + b] = s1[b]; red2[w*8 + b] = s2[b]; }
            }
        }
        __syncthreads();
        if (g < 128) {
            #pragma unroll
            for (int b = 0; b < 8; b++) {
                float mean = (red1[b] + red1[8+b] + red1[16+b] + red1[24+b]) * 0.0078125f;
                float msq  = (red2[b] + red2[8+b] + red2[16+b] + red2[24+b]) * 0.0078125f;
                float var  = msq - mean*mean;
                float rstd = rsqrtf(var + 1e-5f);
                int bm = (bg*8 + b)*16 + n;
                g_Hc[((size_t)bm*256 + t)*144 + g] = __float2half((hnew[b] - mean)*rstd*lg[g] + lb[g]);
            }
        } else if (g < 136) {
            float uv = g_utab[t*8 + (g - 128)];
            #pragma unroll
            for (int b = 0; b < 8; b++) {
                int bm = (bg*8 + b)*16 + n;
                g_Hc[((size_t)bm*256 + t)*144 + g] = __float2half(uv);
            }
        } else if (g < 144) {
            #pragma unroll
            for (int b = 0; b < 8; b++) {
                int bm = (bg*8 + b)*16 + n;
                g_Hc[((size_t)bm*256 + t)*144 + g] = __float2half(0.f);
            }
        }
        __syncthreads();
    }
}

// ---------------- K3: P = Hc @ Wcat^T via HMMA  (262144 x 144) @ (144 x 256) ----------------
__global__ void __launch_bounds__(256) k3_hgemm()
{
    extern __shared__ __half smh[];
    const int PITCH = 168;
    __half* As = smh;
    __half* Bs = smh + 128*PITCH;
    int tid = threadIdx.x;
    size_t row0 = (size_t)blockIdx.x * 128;
    int col0 = blockIdx.y * 128;
    for (int i = tid; i < 128*18; i += 256) {
        int r = i / 18, c = i % 18;
        *(int4*)(As + r*PITCH + c*8) = *(const int4*)(g_Hc + (row0 + r)*144 + c*8);
    }
    for (int i = tid; i < 128*18; i += 256) {
        int r = i / 18, c = i % 18;
        *(int4*)(Bs + r*PITCH + c*8) = *(const int4*)(g_WcatH + (size_t)(col0 + r)*144 + c*8);
    }
    __syncthreads();
    int w = tid >> 5, l = tid & 31;
    int wm = w & 1, wn = w >> 1;
    int lr = l >> 2, lk = (l & 3)*2;
    float c[4][4][4];
    #pragma unroll
    for (int mi = 0; mi < 4; mi++)
        #pragma unroll
        for (int ni = 0; ni < 4; ni++)
            #pragma unroll
            for (int q = 0; q < 4; q++) c[mi][ni][q] = 0.f;
    #pragma unroll
    for (int kc = 0; kc < 9; kc++) {
        int k0 = kc*16;
        uint32_t a[4][4], b[4][2];
        #pragma unroll
        for (int mi = 0; mi < 4; mi++) {
            const __half* ap = As + (wm*64 + mi*16 + lr)*PITCH + k0 + lk;
            a[mi][0] = *(const uint32_t*)(ap);
            a[mi][1] = *(const uint32_t*)(ap + 8*PITCH);
            a[mi][2] = *(const uint32_t*)(ap + 8);
            a[mi][3] = *(const uint32_t*)(ap + 8*PITCH + 8);
        }
        #pragma unroll
        for (int ni = 0; ni < 4; ni++) {
            const __half* bp = Bs + (wn*32 + ni*8 + lr)*PITCH + k0 + lk;
            b[ni][0] = *(const uint32_t*)(bp);
            b[ni][1] = *(const uint32_t*)(bp + 8);
        }
        #pragma unroll
        for (int mi = 0; mi < 4; mi++)
            #pragma unroll
            for (int ni = 0; ni < 4; ni++)
                mma16816(c[mi][ni], a[mi], b[ni]);
    }
    #pragma unroll
    for (int mi = 0; mi < 4; mi++) {
        size_t ra = row0 + wm*64 + mi*16 + lr;
        #pragma unroll
        for (int ni = 0; ni < 4; ni++) {
            int cc = col0 + wn*32 + ni*8 + lk;
            *(__half2*)(g_P + ra*256 + cc)     = __floats2half2_rn(c[mi][ni][0], c[mi][ni][1]);
            *(__half2*)(g_P + (ra+8)*256 + cc) = __floats2half2_rn(c[mi][ni][2], c[mi][ni][3]);
        }
    }
}

// ---------------- K4: graph mix + self + leaky -> Z (fp16 IO) ----------------
__global__ void __launch_bounds__(256) k4_mix(const int* __restrict__ phases)
{
    __shared__ float Am[256], sP[2048];
    int tid = threadIdx.x; int b = blockIdx.y; int t0 = blockIdx.x*8;
    Am[tid] = g_Aph[phases[b]*256 + tid];
    for (int tc = 0; tc < 8; tc++) {
        int t = t0 + tc;
        __syncthreads();
        for (int idx = tid; idx < 2048; idx += 256) { int j = idx >> 7, d = idx & 127;
            sP[idx] = __half2float(g_P[((size_t)(b*16 + j)*256 + t)*256 + d]); }
        __syncthreads();
        for (int idx = tid; idx < 2048; idx += 256) {
            int i = idx >> 7, d = idx & 127;
            size_t row = (size_t)(b*16 + i)*256 + t;
            float accv = __half2float(g_P[row*256 + 128 + d]);
            #pragma unroll
            for (int j = 0; j < 16; j++) accv = fmaf(Am[i*16 + j], sP[j*128 + d], accv);
            g_Z[row*128 + d] = __float2half((accv >= 0.f) ? accv : 0.1f*accv);
        }
    }
}

// ---------------- K5: K|V = Z @ Wkv^T via HMMA; K fp16 [m][d][t], V fp16 [m][t][d] ----------------
__global__ void __launch_bounds__(256) k5_hgemm()
{
    extern __shared__ __half smh[];
    const int PITCH = 136;
    __half* As = smh;
    __half* Bs = smh + 128*PITCH;
    int tid = threadIdx.x;
    size_t row0 = (size_t)blockIdx.x * 128;
    int col0 = blockIdx.y * 128;
    for (int i = tid; i < 128*16; i += 256) {
        int r = i >> 4, c = i & 15;
        *(int4*)(As + r*PITCH + c*8) = *(const int4*)(g_Z + (row0 + r)*128 + c*8);
    }
    for (int i = tid; i < 128*16; i += 256) {
        int r = i >> 4, c = i & 15;
        *(int4*)(Bs + r*PITCH + c*8) = *(const int4*)(g_WkvH + (size_t)(col0 + r)*128 + c*8);
    }
    __syncthreads();
    int w = tid >> 5, l = tid & 31;
    int wm = w & 1, wn = w >> 1;
    int lr = l >> 2, lk = (l & 3)*2;
    float c[4][4][4];
    #pragma unroll
    for (int mi = 0; mi < 4; mi++)
        #pragma unroll
        for (int ni = 0; ni < 4; ni++)
            #pragma unroll
            for (int q = 0; q < 4; q++) c[mi][ni][q] = 0.f;
    #pragma unroll
    for (int kc = 0; kc < 8; kc++) {
        int k0 = kc*16;
        uint32_t a[4][4], b[4][2];
        #pragma unroll
        for (int mi = 0; mi < 4; mi++) {
            const __half* ap = As + (wm*64 + mi*16 + lr)*PITCH + k0 + lk;
            a[mi][0] = *(const uint32_t*)(ap);
            a[mi][1] = *(const uint32_t*)(ap + 8*PITCH);
            a[mi][2] = *(const uint32_t*)(ap + 8);
            a[mi][3] = *(const uint32_t*)(ap + 8*PITCH + 8);
        }
        #pragma unroll
        for (int ni = 0; ni < 4; ni++) {
            const __half* bp = Bs + (wn*32 + ni*8 + lr)*PITCH + k0 + lk;
            b[ni][0] = *(const uint32_t*)(bp);
            b[ni][1] = *(const uint32_t*)(bp + 8);
        }
        #pragma unroll
        for (int mi = 0; mi < 4; mi++)
            #pragma unroll
            for (int ni = 0; ni < 4; ni++)
                mma16816(c[mi][ni], a[mi], b[ni]);
    }
    #pragma unroll
    for (int mi = 0; mi < 4; mi++) {
        size_t ra = row0 + wm*64 + mi*16 + lr;
        size_t rb = ra + 8;
        int ma = (int)(ra >> 8), ta = (int)(ra & 255);
        int tb2 = (int)(rb & 255);
        #pragma unroll
        for (int ni = 0; ni < 4; ni++) {
            int cc = wn*32 + ni*8 + lk;
            if (blockIdx.y == 0) {
                __half* kb = g_K + (size_t)ma*32768;
                kb[(size_t)cc*256 + ta]     = __float2half(c[mi][ni][0]);
                kb[(size_t)(cc+1)*256 + ta] = __float2half(c[mi][ni][1]);
                kb[(size_t)cc*256 + tb2]     = __float2half(c[mi][ni][2]);
                kb[(size_t)(cc+1)*256 + tb2] = __float2half(c[mi][ni][3]);
            } else {
                *(__half2*)(g_V + ra*128 + cc) = __floats2half2_rn(c[mi][ni][0], c[mi][ni][1]);
                *(__half2*)(g_V + rb*128 + cc) = __floats2half2_rn(c[mi][ni][2], c[mi][ni][3]);
            }
        }
    }
}

// ---------------- K6: decode init ----------------
__global__ void k6_init()
{
    int i = blockIdx.x*256 + threadIdx.x;
    if (i < 1024*128) { int m = i >> 7, d = i & 127;
        g_h[i] = __half2float(g_Z[((size_t)m*256 + 255)*128 + d]); }
    if (i < 1024*16) { g_yA[i] = 0.f; g_yB[i] = 0.f; }
}

// ---------------- D-S1: y-mix + attention -> g_ctx, g_ymix ----------------
__global__ void __launch_bounds__(256) d_s1(const int* __restrict__ phases, int step)
{
    __shared__ float ys[256], h_s[128], sc[256], arow[16], wred[8];
    int tid = threadIdx.x; int m = blockIdx.x; int b = m >> 4, n = m & 15;
    const float* y_in = (step & 1) ? g_yB : g_yA;
    ys[tid] = y_in[b*256 + tid];
    if (tid < 16) arow[tid] = g_Aph[phases[b]*256 + n*16 + tid];
    if (tid < 128) h_s[tid] = g_h[m*128 + tid];
    __syncthreads();
    if (tid < 16) {
        float a = 0.f;
        #pragma unroll
        for (int j = 0; j < 16; j++) a = fmaf(arow[j], ys[j*16 + tid], a);
        g_ymix[m*16 + tid] = ys[n*16 + tid] + 0.3f*a;
    }
    const __half* kp = g_K + (size_t)m*32768 + tid;
    float s = 0.f;
    #pragma unroll 8
    for (int d = 0; d < 128; d++) s = fmaf(__half2float(kp[(size_t)d*256]), h_s[d], s);
    s *= g_scale[0];
    int lane = tid & 31, wid = tid >> 5;
    float wm = s;
    #pragma unroll
    for (int o = 16; o > 0; o >>= 1) wm = fmaxf(wm, __shfl_xor_sync(0xffffffffu, wm, o));
    if (lane == 0) wred[wid] = wm;
    __syncthreads();
    float mx = wred[0];
    #pragma unroll
    for (int w = 1; w < 8; w++) mx = fmaxf(mx, wred[w]);
    float e = expf(s - mx);
    float wsum = e;
    #pragma unroll
    for (int o = 16; o > 0; o >>= 1) wsum += __shfl_xor_sync(0xffffffffu, wsum, o);
    __syncthreads();
    if (lane == 0) wred[wid] = wsum;
    __syncthreads();
    float tot = 0.f;
    #pragma unroll
    for (int w = 0; w < 8; w++) tot += wred[w];
    sc[tid] = e * (1.0f / tot);
    __syncthreads();
    int d = tid & 127, half = tid >> 7;
    const __half* vp = g_V + ((size_t)m*256 + half*128)*128 + d;
    float accv = 0.f;
    #pragma unroll 8
    for (int tt = 0; tt < 128; tt++) accv = fmaf(sc[half*128 + tt], __half2float(vp[(size_t)tt*128]), accv);
    __syncthreads();
    ys[tid] = accv;
    __syncthreads();
    if (tid < 128) g_ctx[m*128 + tid] = ys[tid] + ys[tid + 128];
}

// ---------------- D-S2: tiled GRU cell + readout (8 m per block, packed f32x2) ----------------
__global__ void __launch_bounds__(384) d_s2(const float* __restrict__ X,
                                            const float* __restrict__ cbih,
                                            const float* __restrict__ cbhh,
                                            const float* __restrict__ readW,
                                            const float* __restrict__ readb,
                                            float* __restrict__ out, int step)
{
    __shared__ float inA[144*8];
    __shared__ float hS [128*8];
    __shared__ float sA[128*8], sB[128*8], sXn[128*8], sHn[128*8], hn[128*8];
    int tid = threadIdx.x; int m0 = blockIdx.x * 8;
    float* y_out = (step & 1) ? g_yA : g_yB;

    for (int i = tid; i < 144*8; i += 384) {
        int mm = i & 7, k = i >> 3;
        inA[i] = (k < 128) ? g_ctx[(m0 + mm)*128 + k] : g_ymix[(m0 + mm)*16 + (k - 128)];
    }
    for (int i = tid; i < 128*8; i += 384) {
        int mm = i & 7, k = i >> 3;
        hS[i] = g_h[(m0 + mm)*128 + k];
    }
    __syncthreads();

    unsigned inbase = (unsigned)__cvta_generic_to_shared(inA);
    unsigned hbase2 = (unsigned)__cvta_generic_to_shared(hS);

    int g = tid;
    unsigned long long x01, x23, x45, x67, h01v, h23v, h45v, h67v;
    unsigned long long gx01 = pack2(cbih[g]);
    unsigned long long gx23 = gx01, gx45 = gx01, gx67 = gx01;
    unsigned long long gh01 = pack2(cbhh[g]);
    unsigned long long gh23 = gh01, gh45 = gh01, gh67 = gh01;
    const float* wi = g_cWihT + g;
    #pragma unroll 8
    for (int k = 0; k < 144; k++) {
        unsigned long long w2 = pack2(wi[(size_t)k*384]);
        unsigned a0 = inbase + (unsigned)(k*32);
        lds_v2u64(a0, x01, x23);
        lds_v2u64(a0 + 16u, x45, x67);
        fma2(gx01, w2, x01); fma2(gx23, w2, x23);
        fma2(gx45, w2, x45); fma2(gx67, w2, x67);
    }
    const float* wh = g_cWhhT + g;
    #pragma unroll 8
    for (int k = 0; k < 128; k++) {
        unsigned long long w2 = pack2(wh[(size_t)k*384]);
        unsigned a0 = hbase2 + (unsigned)(k*32);
        lds_v2u64(a0, h01v, h23v);
        lds_v2u64(a0 + 16u, h45v, h67v);
        fma2(gh01, w2, h01v); fma2(gh23, w2, h23v);
        fma2(gh45, w2, h45v); fma2(gh67, w2, h67v);
    }
    float gxv[8], ghv[8];
    unpack2(gx01, gxv[0], gxv[1]); unpack2(gx23, gxv[2], gxv[3]);
    unpack2(gx45, gxv[4], gxv[5]); unpack2(gx67, gxv[6], gxv[7]);
    unpack2(gh01, ghv[0], ghv[1]); unpack2(gh23, ghv[2], ghv[3]);
    unpack2(gh45, ghv[4], ghv[5]); unpack2(gh67, ghv[6], ghv[7]);
    if (g < 128) {
        #pragma unroll
        for (int mm = 0; mm < 8; mm++) sA[g*8 + mm] = gxv[mm] + ghv[mm];
    } else if (g < 256) {
        #pragma unroll
        for (int mm = 0; mm < 8; mm++) sB[(g-128)*8 + mm] = gxv[mm] + ghv[mm];
    } else {
        #pragma unroll
        for (int mm = 0; mm < 8; mm++) { sXn[(g-256)*8 + mm] = gxv[mm]; sHn[(g-256)*8 + mm] = ghv[mm]; }
    }
    __syncthreads();
    if (g < 128) {
        #pragma unroll
        for (int mm = 0; mm < 8; mm++) {
            float r  = sigm(sA[g*8 + mm]);
            float z  = sigm(sB[g*8 + mm]);
            float nn = tanhf(sXn[g*8 + mm] + r*sHn[g*8 + mm]);
            float hv = (1.f - z)*nn + z*hS[g*8 + mm];
            g_h[(m0 + mm)*128 + g] = hv;
            hn[g*8 + mm] = hv;
        }
    }
    __syncthreads();
    if (g < 128) {
        int c = g >> 3, r8 = g & 7;
        float a[8];
        #pragma unroll
        for (int mm = 0; mm < 8; mm++) a[mm] = 0.f;
        const float* rw = readW + c*128 + r8*16;
        #pragma unroll
        for (int i = 0; i < 16; i++) {
            float w = rw[i];
            const float* hp = hn + (r8*16 + i)*8;
            #pragma unroll
            for (int mm = 0; mm < 8; mm++) a[mm] = fmaf(w, hp[mm], a[mm]);
        }
        #pragma unroll
        for (int mm = 0; mm < 8; mm++) {
            a[mm] += __shfl_down_sync(0xffffffffu, a[mm], 4, 8);
            a[mm] += __shfl_down_sync(0xffffffffu, a[mm], 2, 8);
            a[mm] += __shfl_down_sync(0xffffffffu, a[mm], 1, 8);
        }
        if (r8 == 0) {
            float rb = readb[c];
            #pragma unroll
            for (int mm = 0; mm < 8; mm++) {
                int mc = (m0 + mm)*16 + c;
                float yt = a[mm] + rb + inA[(128 + c)*8 + mm];
                y_out[mc] = yt;
                float vv = X[(size_t)mc*256 + 255] + yt;
                out[mc*32 + step] = vv;
                if (step == 0) out[524288 + mc] = vv;
            }
        }
    }
}

// ---------------- host launch ----------------
extern "C" void kernel_launch(void* const* d_in, const int* in_sizes, int n_in,
                              void* d_out, int out_size)
{
    const float* X      = (const float*)d_in[0];
    const int*   phases = (const int*)  d_in[1];
    const float* gWih   = (const float*)d_in[2];
    const float* gWhh   = (const float*)d_in[3];
    const float* gbih   = (const float*)d_in[4];
    const float* gbhh   = (const float*)d_in[5];
    const float* lng    = (const float*)d_in[6];
    const float* lnb    = (const float*)d_in[7];
    const float* tW     = (const float*)d_in[8];
    const float* tb     = (const float*)d_in[9];
    const float* S      = (const float*)d_in[10];
    const float* G      = (const float*)d_in[11];
    const float* Wself  = (const float*)d_in[12];
    const float* Wneigh = (const float*)d_in[13];
    const float* cWih   = (const float*)d_in[14];
    const float* cWhh   = (const float*)d_in[15];
    const float* cbih   = (const float*)d_in[16];
    const float* cbhh   = (const float*)d_in[17];
    const float* readW  = (const float*)d_in[18];
    const float* readb  = (const float*)d_in[19];
    const float* Wk     = (const float*)d_in[20];
    const float* Wv     = (const float*)d_in[21];
    const float* ltau   = (const float*)d_in[22];
    float* out = (float*)d_out;

    const int k2_smem = K2_SMEM_FLOATS * (int)sizeof(float);
    const int k3_smem = 2 * 128 * 168 * (int)sizeof(__half);  // 86016
    const int k5_smem = 2 * 128 * 136 * (int)sizeof(__half);  // 69632
    cudaFuncSetAttribute(k2_gru, cudaFuncAttributeMaxDynamicSharedMemorySize, k2_smem);
    cudaFuncSetAttribute(k3_hgemm, cudaFuncAttributeMaxDynamicSharedMemorySize, k3_smem);
    cudaFuncSetAttribute(k5_hgemm, cudaFuncAttributeMaxDynamicSharedMemorySize, k5_smem);

    k0_prep<<<1, 256>>>(Wneigh, Wself, Wk, Wv, S, G, tW, tb, ltau);
    {
        int total = 16*384*128 + 384*144 + 384*128;
        k_trans<<<(total + 255)/256, 256>>>(gWhh, cWih, cWhh);
    }
    k2_gru<<<128, 384, k2_smem>>>(X, gWih, gbih, gbhh, lng, lnb);
    k3_hgemm<<<dim3(2048, 2), 256, k3_smem>>>();
    k4_mix<<<dim3(32, 64), 256>>>(phases);
    k5_hgemm<<<dim3(2048, 2), 256, k5_smem>>>();
    k6_init<<<512, 256>>>();
    for (int s = 0; s < 32; s++) {
        d_s1<<<1024, 256>>>(phases, s);
        d_s2<<<128, 384>>>(X, cbih, cbhh, readW, readb, out, s);
    }
    (void)in_sizes; (void)n_in; (void)out_size;
}